// round 2
// baseline (speedup 1.0000x reference)
#include <cuda_runtime.h>
#include <cuda_bf16.h>

#define DM 1024
#define NH 16
#define DH 64
#define BB 2
#define TT 2048
#define MT (BB*TT)   // 4096 rows total

// ---- scratch (no allocations allowed) ----
__device__ float g_q[MT*DM];
__device__ float g_k[MT*DM];
__device__ float g_v[MT*DM];
__device__ float g_y[MT*DM];
__device__ float g_yn[MT*DM];
__device__ float g_stats[BB*NH*2];

// ============================================================
// SGEMM: C[M,N] = A[M,K] @ Bm[N,K]^T   (torch Linear semantics)
// 128x128 block tile, BK=8, 8x8 microtile, 256 threads
// ============================================================
__global__ __launch_bounds__(256, 2)
void sgemm_nt(const float* __restrict__ A, const float* __restrict__ Bm,
              float* __restrict__ C, int M, int N, int K)
{
    __shared__ float As[8][132];
    __shared__ float Bs[8][132];
    const int tid = threadIdx.x;
    const int m0 = blockIdx.y * 128;
    const int n0 = blockIdx.x * 128;
    const int tr = tid >> 4;        // 0..15
    const int tc = tid & 15;        // 0..15
    const int lrow = tid >> 1;      // 0..127
    const int lk = (tid & 1) * 4;   // 0 or 4

    float acc[8][8];
    #pragma unroll
    for (int i = 0; i < 8; i++)
        #pragma unroll
        for (int j = 0; j < 8; j++) acc[i][j] = 0.f;

    const float* Aptr = A + (size_t)(m0 + lrow) * K + lk;
    const float* Bptr = Bm + (size_t)(n0 + lrow) * K + lk;

    for (int k0 = 0; k0 < K; k0 += 8) {
        float4 a4 = *(const float4*)(Aptr + k0);
        float4 b4 = *(const float4*)(Bptr + k0);
        As[lk+0][lrow] = a4.x; As[lk+1][lrow] = a4.y;
        As[lk+2][lrow] = a4.z; As[lk+3][lrow] = a4.w;
        Bs[lk+0][lrow] = b4.x; Bs[lk+1][lrow] = b4.y;
        Bs[lk+2][lrow] = b4.z; Bs[lk+3][lrow] = b4.w;
        __syncthreads();
        #pragma unroll
        for (int kk = 0; kk < 8; kk++) {
            float ar[8], br[8];
            *(float4*)&ar[0] = *(const float4*)&As[kk][tr*8];
            *(float4*)&ar[4] = *(const float4*)&As[kk][tr*8+4];
            *(float4*)&br[0] = *(const float4*)&Bs[kk][tc*8];
            *(float4*)&br[4] = *(const float4*)&Bs[kk][tc*8+4];
            #pragma unroll
            for (int i = 0; i < 8; i++)
                #pragma unroll
                for (int j = 0; j < 8; j++)
                    acc[i][j] += ar[i] * br[j];
        }
        __syncthreads();
    }
    #pragma unroll
    for (int i = 0; i < 8; i++) {
        float* crow = C + (size_t)(m0 + tr*8 + i) * N + n0 + tc*8;
        *(float4*)(crow)   = make_float4(acc[i][0], acc[i][1], acc[i][2], acc[i][3]);
        *(float4*)(crow+4) = make_float4(acc[i][4], acc[i][5], acc[i][6], acc[i][7]);
    }
}

// ============================================================
// Retention: per (b,h), i-tile of 128 q rows; loop over j-tiles of 64.
// S = (Q*γ^ir) @ (K*γ^-jr)^T * γ^(i0-j0)/8, masked; y += S @ V
// ============================================================
#define RET_SMEM_FLOATS (64*132 + 64*68 + 64*68 + 128*68)

__global__ __launch_bounds__(256)
void retention(const float* __restrict__ q, const float* __restrict__ kmat,
               const float* __restrict__ vmat, float* __restrict__ y)
{
    extern __shared__ float sm[];
    float (*QT)[132] = (float (*)[132])sm;                        // [64][132] : [c][i]
    float (*KT)[68]  = (float (*)[68])(sm + 64*132);              // [64][68]  : [c][j]
    float (*Vs)[68]  = (float (*)[68])(sm + 64*132 + 64*68);      // [64][68]  : [j][c]
    float (*Ss)[68]  = (float (*)[68])(sm + 64*132 + 2*64*68);    // [128][68] : [i][j]

    const int it = blockIdx.x;
    const int bh = blockIdx.y;
    const int b = bh >> 4, h = bh & 15;
    const int i0 = it * 128;
    const float gamma = 1.f - exp2f(-5.f - (float)h);
    const float lg = log2f(gamma);
    const int tid = threadIdx.x;
    const int tr = tid >> 4;   // 0..15 (8 i-rows each)
    const int tc = tid & 15;   // 0..15 (4 cols each)

    // load Q tile [128 x 64], transposed into QT[c][i], scaled by gamma^(i-i0)
    const float* qbase = q + ((size_t)(b*TT + i0))*DM + h*DH;
    for (int s = tid; s < 128*16; s += 256) {
        int row = s >> 4, c4 = (s & 15) << 2;
        float4 a = *(const float4*)(qbase + (size_t)row*DM + c4);
        float sc = exp2f(lg * (float)row);
        QT[c4+0][row] = a.x*sc; QT[c4+1][row] = a.y*sc;
        QT[c4+2][row] = a.z*sc; QT[c4+3][row] = a.w*sc;
    }

    float accy[8][4];
    #pragma unroll
    for (int i = 0; i < 8; i++)
        #pragma unroll
        for (int j = 0; j < 4; j++) accy[i][j] = 0.f;

    const int njt = 2 * (it + 1);
    for (int jt = 0; jt < njt; jt++) {
        const int j0 = jt << 6;
        const int diffbase = i0 - j0;      // >= -64
        const float* kbase = kmat + ((size_t)(b*TT + j0))*DM + h*DH;
        const float* vbase = vmat + ((size_t)(b*TT + j0))*DM + h*DH;
        __syncthreads();   // prev GEMM2 reads done before overwriting tiles
        for (int s = tid; s < 64*16; s += 256) {
            int row = s >> 4, c4 = (s & 15) << 2;
            float sc = exp2f(-lg * (float)row);   // gamma^-(j-j0)
            float4 kk = *(const float4*)(kbase + (size_t)row*DM + c4);
            KT[c4+0][row] = kk.x*sc; KT[c4+1][row] = kk.y*sc;
            KT[c4+2][row] = kk.z*sc; KT[c4+3][row] = kk.w*sc;
            float4 vv = *(const float4*)(vbase + (size_t)row*DM + c4);
            *(float4*)&Vs[row][c4] = vv;
        }
        __syncthreads();

        // GEMM1: S[ir][jr] = sum_c QT[c][ir]*KT[c][jr]
        float acc1[8][4];
        #pragma unroll
        for (int i = 0; i < 8; i++)
            #pragma unroll
            for (int j = 0; j < 4; j++) acc1[i][j] = 0.f;
        #pragma unroll 8
        for (int c = 0; c < 64; c++) {
            float ar[8], br[4];
            *(float4*)&ar[0] = *(const float4*)&QT[c][tr*8];
            *(float4*)&ar[4] = *(const float4*)&QT[c][tr*8+4];
            *(float4*)&br[0] = *(const float4*)&KT[c][tc*4];
            #pragma unroll
            for (int i = 0; i < 8; i++)
                #pragma unroll
                for (int j = 0; j < 4; j++)
                    acc1[i][j] += ar[i] * br[j];
        }

        const float base = exp2f(lg * (float)diffbase) * 0.125f;  // gamma^(i0-j0)/sqrt(64)
        const bool needmask = (diffbase < 128);
        #pragma unroll
        for (int i = 0; i < 8; i++) {
            const int ir = tr*8 + i;
            float o0 = acc1[i][0]*base, o1 = acc1[i][1]*base;
            float o2 = acc1[i][2]*base, o3 = acc1[i][3]*base;
            if (needmask) {
                int d0 = diffbase + ir - (tc*4);
                if (d0     < 0) o0 = 0.f;
                if (d0 - 1 < 0) o1 = 0.f;
                if (d0 - 2 < 0) o2 = 0.f;
                if (d0 - 3 < 0) o3 = 0.f;
            }
            *(float4*)&Ss[ir][tc*4] = make_float4(o0, o1, o2, o3);
        }
        __syncthreads();

        // GEMM2: y[ir][c] += sum_jr Ss[ir][jr]*Vs[jr][c]
        #pragma unroll 8
        for (int jr = 0; jr < 64; jr++) {
            float br[4];
            *(float4*)&br[0] = *(const float4*)&Vs[jr][tc*4];
            #pragma unroll
            for (int i = 0; i < 8; i++) {
                float sv = Ss[tr*8+i][jr];
                accy[i][0] += sv * br[0];
                accy[i][1] += sv * br[1];
                accy[i][2] += sv * br[2];
                accy[i][3] += sv * br[3];
            }
        }
    }

    float* ybase = y + ((size_t)(b*TT + i0))*DM + h*DH;
    #pragma unroll
    for (int i = 0; i < 8; i++) {
        *(float4*)(ybase + (size_t)(tr*8 + i)*DM + tc*4) =
            make_float4(accy[i][0], accy[i][1], accy[i][2], accy[i][3]);
    }
}

// ============================================================
// GroupNorm: one block per (b,h) reduces T*DH; then elementwise apply
// ============================================================
__global__ void gn_reduce(const float* __restrict__ y, float* __restrict__ stats)
{
    const int bh = blockIdx.x;
    const int b = bh >> 4, h = bh & 15;
    const float* base = y + (size_t)b*TT*DM + h*DH;
    float s = 0.f, s2 = 0.f;
    for (int sl = threadIdx.x; sl < TT*16; sl += blockDim.x) {
        int t = sl >> 4, c4 = (sl & 15) << 2;
        float4 vv = *(const float4*)(base + (size_t)t*DM + c4);
        s  += vv.x + vv.y + vv.z + vv.w;
        s2 += vv.x*vv.x + vv.y*vv.y + vv.z*vv.z + vv.w*vv.w;
    }
    #pragma unroll
    for (int o = 16; o > 0; o >>= 1) {
        s  += __shfl_down_sync(0xffffffffu, s,  o);
        s2 += __shfl_down_sync(0xffffffffu, s2, o);
    }
    __shared__ float rs[32], rs2[32];
    const int wid = threadIdx.x >> 5, lid = threadIdx.x & 31;
    if (lid == 0) { rs[wid] = s; rs2[wid] = s2; }
    __syncthreads();
    if (wid == 0) {
        const int nw = blockDim.x >> 5;
        s  = (lid < nw) ? rs[lid]  : 0.f;
        s2 = (lid < nw) ? rs2[lid] : 0.f;
        #pragma unroll
        for (int o = 16; o > 0; o >>= 1) {
            s  += __shfl_down_sync(0xffffffffu, s,  o);
            s2 += __shfl_down_sync(0xffffffffu, s2, o);
        }
        if (lid == 0) {
            const float invN = 1.f / (float)(TT * DH);
            float mean = s * invN;
            float var = s2 * invN - mean * mean;
            stats[bh*2]   = mean;
            stats[bh*2+1] = rsqrtf(var + 1e-5f);
        }
    }
}

__global__ void gn_apply(const float* __restrict__ y, const float* __restrict__ stats,
                         const float* __restrict__ gw, const float* __restrict__ gb,
                         float* __restrict__ yn)
{
    size_t e = ((size_t)blockIdx.x * blockDim.x + threadIdx.x) * 4;
    int col = (int)(e % DM);
    size_t row = e / DM;
    int b = (int)(row / TT);
    int g = b * 16 + (col >> 6);
    float mean = stats[g*2], rstd = stats[g*2+1];
    float4 vv = *(const float4*)(y + e);
    float4 w4 = *(const float4*)(gw + col);
    float4 b4 = *(const float4*)(gb + col);
    float4 o;
    o.x = (vv.x - mean) * rstd * w4.x + b4.x;
    o.y = (vv.y - mean) * rstd * w4.y + b4.y;
    o.z = (vv.z - mean) * rstd * w4.z + b4.z;
    o.w = (vv.w - mean) * rstd * w4.w + b4.w;
    *(float4*)(yn + e) = o;
}

// ============================================================
extern "C" void kernel_launch(void* const* d_in, const int* in_sizes, int n_in,
                              void* d_out, int out_size)
{
    const float* x  = (const float*)d_in[0];
    const float* Wq = (const float*)d_in[1];
    const float* Wk = (const float*)d_in[2];
    const float* Wv = (const float*)d_in[3];
    const float* Wo = (const float*)d_in[4];
    const float* gw = (const float*)d_in[5];
    const float* gb = (const float*)d_in[6];
    float* out = (float*)d_out;

    float *q, *k, *v, *y, *yn, *st;
    cudaGetSymbolAddress((void**)&q,  g_q);
    cudaGetSymbolAddress((void**)&k,  g_k);
    cudaGetSymbolAddress((void**)&v,  g_v);
    cudaGetSymbolAddress((void**)&y,  g_y);
    cudaGetSymbolAddress((void**)&yn, g_yn);
    cudaGetSymbolAddress((void**)&st, g_stats);

    const int ret_smem = RET_SMEM_FLOATS * (int)sizeof(float);
    cudaFuncSetAttribute(retention, cudaFuncAttributeMaxDynamicSharedMemorySize, ret_smem);

    dim3 gg(DM/128, MT/128);   // (8, 32)
    sgemm_nt<<<gg, 256>>>(x, Wq, q, MT, DM, DM);
    sgemm_nt<<<gg, 256>>>(x, Wk, k, MT, DM, DM);
    sgemm_nt<<<gg, 256>>>(x, Wv, v, MT, DM, DM);

    retention<<<dim3(TT/128, BB*NH), 256, ret_smem>>>(q, k, v, y);

    gn_reduce<<<BB*NH, 512>>>(y, st);
    gn_apply<<<(MT*DM)/(4*256), 256>>>(y, st, gw, gb, yn);

    sgemm_nt<<<gg, 256>>>(yn, Wo, out, MT, DM, DM);
}

// round 3
// speedup vs baseline: 1.4342x; 1.4342x over previous
#include <cuda_runtime.h>
#include <cuda_bf16.h>

#define DM 1024
#define NH 16
#define DH 64
#define BB 2
#define TT 2048
#define MT (BB*TT)    // 4096 rows total
#define CH 128        // chunk size
#define NC (TT/CH)    // 16 chunks

// ---- scratch (no allocations allowed) ----
__device__ float g_q[MT*DM];
__device__ float g_k[MT*DM];
__device__ float g_v[MT*DM];
__device__ float g_y[MT*DM];
__device__ float g_yn[MT*DM];
__device__ float g_stats[BB*NH*2];
__device__ float g_P[BB*NH*NC*DH*DH];   // per-chunk partial states
__device__ float g_S[BB*NH*NC*DH*DH];   // scanned states (pre-scaled by 1/8)

// ============================================================
// SGEMM: C[M,N] = A[M,K] @ Bm[N,K]^T   (torch Linear semantics)
// ============================================================
__global__ __launch_bounds__(256, 2)
void sgemm_nt(const float* __restrict__ A, const float* __restrict__ Bm,
              float* __restrict__ C, int M, int N, int K)
{
    __shared__ float As[8][132];
    __shared__ float Bs[8][132];
    const int tid = threadIdx.x;
    const int m0 = blockIdx.y * 128;
    const int n0 = blockIdx.x * 128;
    const int tr = tid >> 4;
    const int tc = tid & 15;
    const int lrow = tid >> 1;
    const int lk = (tid & 1) * 4;

    float acc[8][8];
    #pragma unroll
    for (int i = 0; i < 8; i++)
        #pragma unroll
        for (int j = 0; j < 8; j++) acc[i][j] = 0.f;

    const float* Aptr = A + (size_t)(m0 + lrow) * K + lk;
    const float* Bptr = Bm + (size_t)(n0 + lrow) * K + lk;

    for (int k0 = 0; k0 < K; k0 += 8) {
        float4 a4 = *(const float4*)(Aptr + k0);
        float4 b4 = *(const float4*)(Bptr + k0);
        As[lk+0][lrow] = a4.x; As[lk+1][lrow] = a4.y;
        As[lk+2][lrow] = a4.z; As[lk+3][lrow] = a4.w;
        Bs[lk+0][lrow] = b4.x; Bs[lk+1][lrow] = b4.y;
        Bs[lk+2][lrow] = b4.z; Bs[lk+3][lrow] = b4.w;
        __syncthreads();
        #pragma unroll
        for (int kk = 0; kk < 8; kk++) {
            float ar[8], br[8];
            *(float4*)&ar[0] = *(const float4*)&As[kk][tr*8];
            *(float4*)&ar[4] = *(const float4*)&As[kk][tr*8+4];
            *(float4*)&br[0] = *(const float4*)&Bs[kk][tc*8];
            *(float4*)&br[4] = *(const float4*)&Bs[kk][tc*8+4];
            #pragma unroll
            for (int i = 0; i < 8; i++)
                #pragma unroll
                for (int j = 0; j < 8; j++)
                    acc[i][j] += ar[i] * br[j];
        }
        __syncthreads();
    }
    #pragma unroll
    for (int i = 0; i < 8; i++) {
        float* crow = C + (size_t)(m0 + tr*8 + i) * N + n0 + tc*8;
        *(float4*)(crow)   = make_float4(acc[i][0], acc[i][1], acc[i][2], acc[i][3]);
        *(float4*)(crow+4) = make_float4(acc[i][4], acc[i][5], acc[i][6], acc[i][7]);
    }
}

// ============================================================
// chunk_state: P[bh][ch] = gamma^CH * sum_j (gamma^-j k_j) v_j^T   (64x64, K=128)
// ============================================================
__global__ __launch_bounds__(256)
void chunk_state(const float* __restrict__ kmat, const float* __restrict__ vmat,
                 float* __restrict__ P)
{
    __shared__ float Ks[CH][68];
    __shared__ float Vs[CH][68];
    const int ch = blockIdx.x;
    const int bh = blockIdx.y;
    const int b = bh >> 4, h = bh & 15;
    const float lg = log2f(1.f - exp2f(-5.f - (float)h));
    const int tid = threadIdx.x;
    const int j0 = ch * CH;

    const float* kbase = kmat + ((size_t)(b*TT + j0))*DM + h*DH;
    const float* vbase = vmat + ((size_t)(b*TT + j0))*DM + h*DH;
    for (int s = tid; s < CH*16; s += 256) {
        int row = s >> 4, c4 = (s & 15) << 2;
        float sc = exp2f(lg * (float)(CH - row));   // gamma^(CH - j)
        float4 kk = *(const float4*)(kbase + (size_t)row*DM + c4);
        Ks[row][c4+0] = kk.x*sc; Ks[row][c4+1] = kk.y*sc;
        Ks[row][c4+2] = kk.z*sc; Ks[row][c4+3] = kk.w*sc;
        float4 vv = *(const float4*)(vbase + (size_t)row*DM + c4);
        *(float4*)&Vs[row][c4] = vv;
    }
    __syncthreads();

    const int tr = tid >> 4, tc = tid & 15;
    float acc[4][4];
    #pragma unroll
    for (int i = 0; i < 4; i++)
        #pragma unroll
        for (int j = 0; j < 4; j++) acc[i][j] = 0.f;

    #pragma unroll 4
    for (int j = 0; j < CH; j++) {
        float ar[4], br[4];
        *(float4*)&ar[0] = *(const float4*)&Ks[j][tr*4];
        *(float4*)&br[0] = *(const float4*)&Vs[j][tc*4];
        #pragma unroll
        for (int i = 0; i < 4; i++)
            #pragma unroll
            for (int jj = 0; jj < 4; jj++)
                acc[i][jj] += ar[i] * br[jj];
    }

    float* pbase = P + ((size_t)(bh*NC + ch))*DH*DH;
    #pragma unroll
    for (int i = 0; i < 4; i++)
        *(float4*)(pbase + (tr*4 + i)*DH + tc*4) =
            make_float4(acc[i][0], acc[i][1], acc[i][2], acc[i][3]);
}

// ============================================================
// state_scan: S[n] = sum_{m<n} gamma^(CH*(n-1-m)) P[m]  via recurrence,
// stored pre-scaled by 1/sqrt(DH)=0.125
// ============================================================
__global__ __launch_bounds__(256)
void state_scan(const float* __restrict__ P, float* __restrict__ S)
{
    const int bh = blockIdx.x;
    const int h = bh & 15;
    const float lg = log2f(1.f - exp2f(-5.f - (float)h));
    const float gC = exp2f(lg * (float)CH);
    const int tid = threadIdx.x;

    float s[16];
    #pragma unroll
    for (int r = 0; r < 16; r++) s[r] = 0.f;

    for (int n = 0; n < NC; n++) {
        const size_t base = ((size_t)(bh*NC + n))*DH*DH;
        #pragma unroll
        for (int r = 0; r < 16; r++)
            S[base + tid + 256*r] = s[r] * 0.125f;
        #pragma unroll
        for (int r = 0; r < 16; r++)
            s[r] = gC * s[r] + P[base + tid + 256*r];
    }
}

// ============================================================
// retention_chunk: per (b,h,chunk): y = Qs @ S_chunk  +  intra-chunk causal part
// Qs rows pre-scaled by gamma^(i_local); K rows by gamma^(-j_local)
// smem: QT 64x132 + KT 64x68 + Vs 64x68 + Ss 128x68 = 103.4KB -> 2 CTAs/SM
// ============================================================
#define RET_SMEM_FLOATS (64*132 + 64*68 + 64*68 + 128*68)

__global__ __launch_bounds__(256)
void retention_chunk(const float* __restrict__ q, const float* __restrict__ kmat,
                     const float* __restrict__ vmat, const float* __restrict__ Sg,
                     float* __restrict__ y)
{
    extern __shared__ float sm[];
    float (*QT)[132] = (float (*)[132])sm;                        // [64][128+] : [c][i]
    float (*KT)[68]  = (float (*)[68])(sm + 64*132);              // [64][68]  : [c][j] (also holds S)
    float (*Vs)[68]  = (float (*)[68])(sm + 64*132 + 64*68);      // [64][68]
    float (*Ss)[68]  = (float (*)[68])(sm + 64*132 + 2*64*68);    // [128][68]

    const int it = blockIdx.x;          // chunk index
    const int bh = blockIdx.y;
    const int b = bh >> 4, h = bh & 15;
    const int i0 = it * CH;
    const float lg = log2f(1.f - exp2f(-5.f - (float)h));
    const int tid = threadIdx.x;
    const int tr = tid >> 4;
    const int tc = tid & 15;

    // load Q tile [128 x 64] transposed + scaled by gamma^(i_local)
    const float* qbase = q + ((size_t)(b*TT + i0))*DM + h*DH;
    for (int s = tid; s < CH*16; s += 256) {
        int row = s >> 4, c4 = (s & 15) << 2;
        float4 a = *(const float4*)(qbase + (size_t)row*DM + c4);
        float sc = exp2f(lg * (float)row);
        QT[c4+0][row] = a.x*sc; QT[c4+1][row] = a.y*sc;
        QT[c4+2][row] = a.z*sc; QT[c4+3][row] = a.w*sc;
    }
    // load state S [64 x 64] into KT (row a = k-dim, col = v-dim)
    const float* sbase = Sg + ((size_t)(bh*NC + it))*DH*DH;
    for (int s = tid; s < 64*16; s += 256) {
        int row = s >> 4, c4 = (s & 15) << 2;
        *(float4*)&KT[row][c4] = *(const float4*)(sbase + row*DH + c4);
    }
    __syncthreads();

    float accy[8][4];
    #pragma unroll
    for (int i = 0; i < 8; i++)
        #pragma unroll
        for (int j = 0; j < 4; j++) accy[i][j] = 0.f;

    // inter-chunk: accy[i][c] += sum_a QT[a][i] * S[a][c]
    #pragma unroll 8
    for (int a = 0; a < DH; a++) {
        float ar[8], br[4];
        *(float4*)&ar[0] = *(const float4*)&QT[a][tr*8];
        *(float4*)&ar[4] = *(const float4*)&QT[a][tr*8+4];
        *(float4*)&br[0] = *(const float4*)&KT[a][tc*4];
        #pragma unroll
        for (int i = 0; i < 8; i++)
            #pragma unroll
            for (int j = 0; j < 4; j++)
                accy[i][j] += ar[i] * br[j];
    }

    // intra-chunk: two 64-wide j-tiles inside this chunk
    #pragma unroll
    for (int jt = 0; jt < 2; jt++) {
        const int j0 = i0 + (jt << 6);
        const int diffbase = -(jt << 6);
        const float* kbase = kmat + ((size_t)(b*TT + j0))*DM + h*DH;
        const float* vbase = vmat + ((size_t)(b*TT + j0))*DM + h*DH;
        __syncthreads();   // prev reads of KT/Vs done
        for (int s = tid; s < 64*16; s += 256) {
            int row = s >> 4, c4 = (s & 15) << 2;
            float sc = exp2f(-lg * (float)row);   // gamma^-(j_local)
            float4 kk = *(const float4*)(kbase + (size_t)row*DM + c4);
            KT[c4+0][row] = kk.x*sc; KT[c4+1][row] = kk.y*sc;
            KT[c4+2][row] = kk.z*sc; KT[c4+3][row] = kk.w*sc;
            float4 vv = *(const float4*)(vbase + (size_t)row*DM + c4);
            *(float4*)&Vs[row][c4] = vv;
        }
        __syncthreads();

        float acc1[8][4];
        #pragma unroll
        for (int i = 0; i < 8; i++)
            #pragma unroll
            for (int j = 0; j < 4; j++) acc1[i][j] = 0.f;
        #pragma unroll 8
        for (int c = 0; c < DH; c++) {
            float ar[8], br[4];
            *(float4*)&ar[0] = *(const float4*)&QT[c][tr*8];
            *(float4*)&ar[4] = *(const float4*)&QT[c][tr*8+4];
            *(float4*)&br[0] = *(const float4*)&KT[c][tc*4];
            #pragma unroll
            for (int i = 0; i < 8; i++)
                #pragma unroll
                for (int j = 0; j < 4; j++)
                    acc1[i][j] += ar[i] * br[j];
        }

        const float base = exp2f(lg * (float)diffbase) * 0.125f;
        #pragma unroll
        for (int i = 0; i < 8; i++) {
            const int ir = tr*8 + i;
            float o0 = acc1[i][0]*base, o1 = acc1[i][1]*base;
            float o2 = acc1[i][2]*base, o3 = acc1[i][3]*base;
            int d0 = diffbase + ir - (tc*4);
            if (d0     < 0) o0 = 0.f;
            if (d0 - 1 < 0) o1 = 0.f;
            if (d0 - 2 < 0) o2 = 0.f;
            if (d0 - 3 < 0) o3 = 0.f;
            *(float4*)&Ss[ir][tc*4] = make_float4(o0, o1, o2, o3);
        }
        __syncthreads();

        #pragma unroll 8
        for (int jr = 0; jr < 64; jr++) {
            float br[4];
            *(float4*)&br[0] = *(const float4*)&Vs[jr][tc*4];
            #pragma unroll
            for (int i = 0; i < 8; i++) {
                float sv = Ss[tr*8+i][jr];
                accy[i][0] += sv * br[0];
                accy[i][1] += sv * br[1];
                accy[i][2] += sv * br[2];
                accy[i][3] += sv * br[3];
            }
        }
    }

    float* ybase = y + ((size_t)(b*TT + i0))*DM + h*DH;
    #pragma unroll
    for (int i = 0; i < 8; i++) {
        *(float4*)(ybase + (size_t)(tr*8 + i)*DM + tc*4) =
            make_float4(accy[i][0], accy[i][1], accy[i][2], accy[i][3]);
    }
}

// ============================================================
// GroupNorm
// ============================================================
__global__ void gn_reduce(const float* __restrict__ y, float* __restrict__ stats)
{
    const int bh = blockIdx.x;
    const int b = bh >> 4, h = bh & 15;
    const float* base = y + (size_t)b*TT*DM + h*DH;
    float s = 0.f, s2 = 0.f;
    for (int sl = threadIdx.x; sl < TT*16; sl += blockDim.x) {
        int t = sl >> 4, c4 = (sl & 15) << 2;
        float4 vv = *(const float4*)(base + (size_t)t*DM + c4);
        s  += vv.x + vv.y + vv.z + vv.w;
        s2 += vv.x*vv.x + vv.y*vv.y + vv.z*vv.z + vv.w*vv.w;
    }
    #pragma unroll
    for (int o = 16; o > 0; o >>= 1) {
        s  += __shfl_down_sync(0xffffffffu, s,  o);
        s2 += __shfl_down_sync(0xffffffffu, s2, o);
    }
    __shared__ float rs[32], rs2[32];
    const int wid = threadIdx.x >> 5, lid = threadIdx.x & 31;
    if (lid == 0) { rs[wid] = s; rs2[wid] = s2; }
    __syncthreads();
    if (wid == 0) {
        const int nw = blockDim.x >> 5;
        s  = (lid < nw) ? rs[lid]  : 0.f;
        s2 = (lid < nw) ? rs2[lid] : 0.f;
        #pragma unroll
        for (int o = 16; o > 0; o >>= 1) {
            s  += __shfl_down_sync(0xffffffffu, s,  o);
            s2 += __shfl_down_sync(0xffffffffu, s2, o);
        }
        if (lid == 0) {
            const float invN = 1.f / (float)(TT * DH);
            float mean = s * invN;
            float var = s2 * invN - mean * mean;
            stats[bh*2]   = mean;
            stats[bh*2+1] = rsqrtf(var + 1e-5f);
        }
    }
}

__global__ void gn_apply(const float* __restrict__ y, const float* __restrict__ stats,
                         const float* __restrict__ gw, const float* __restrict__ gb,
                         float* __restrict__ yn)
{
    size_t e = ((size_t)blockIdx.x * blockDim.x + threadIdx.x) * 4;
    int col = (int)(e % DM);
    size_t row = e / DM;
    int b = (int)(row / TT);
    int g = b * 16 + (col >> 6);
    float mean = stats[g*2], rstd = stats[g*2+1];
    float4 vv = *(const float4*)(y + e);
    float4 w4 = *(const float4*)(gw + col);
    float4 b4 = *(const float4*)(gb + col);
    float4 o;
    o.x = (vv.x - mean) * rstd * w4.x + b4.x;
    o.y = (vv.y - mean) * rstd * w4.y + b4.y;
    o.z = (vv.z - mean) * rstd * w4.z + b4.z;
    o.w = (vv.w - mean) * rstd * w4.w + b4.w;
    *(float4*)(yn + e) = o;
}

// ============================================================
extern "C" void kernel_launch(void* const* d_in, const int* in_sizes, int n_in,
                              void* d_out, int out_size)
{
    const float* x  = (const float*)d_in[0];
    const float* Wq = (const float*)d_in[1];
    const float* Wk = (const float*)d_in[2];
    const float* Wv = (const float*)d_in[3];
    const float* Wo = (const float*)d_in[4];
    const float* gw = (const float*)d_in[5];
    const float* gb = (const float*)d_in[6];
    float* out = (float*)d_out;

    float *q, *k, *v, *y, *yn, *st, *P, *S;
    cudaGetSymbolAddress((void**)&q,  g_q);
    cudaGetSymbolAddress((void**)&k,  g_k);
    cudaGetSymbolAddress((void**)&v,  g_v);
    cudaGetSymbolAddress((void**)&y,  g_y);
    cudaGetSymbolAddress((void**)&yn, g_yn);
    cudaGetSymbolAddress((void**)&st, g_stats);
    cudaGetSymbolAddress((void**)&P,  g_P);
    cudaGetSymbolAddress((void**)&S,  g_S);

    const int ret_smem = RET_SMEM_FLOATS * (int)sizeof(float);
    cudaFuncSetAttribute(retention_chunk, cudaFuncAttributeMaxDynamicSharedMemorySize, ret_smem);

    dim3 gg(DM/128, MT/128);   // (8, 32)
    sgemm_nt<<<gg, 256>>>(x, Wq, q, MT, DM, DM);
    sgemm_nt<<<gg, 256>>>(x, Wk, k, MT, DM, DM);
    sgemm_nt<<<gg, 256>>>(x, Wv, v, MT, DM, DM);

    chunk_state<<<dim3(NC, BB*NH), 256>>>(k, v, P);
    state_scan<<<BB*NH, 256>>>(P, S);
    retention_chunk<<<dim3(NC, BB*NH), 256, ret_smem>>>(q, k, v, S, y);

    gn_reduce<<<BB*NH, 512>>>(y, st);
    gn_apply<<<(MT*DM)/(4*256), 256>>>(y, st, gw, gb, yn);

    sgemm_nt<<<gg, 256>>>(yn, Wo, out, MT, DM, DM);
}

// round 5
// speedup vs baseline: 2.8382x; 1.9789x over previous
#include <cuda_runtime.h>
#include <cuda_bf16.h>
#include <cstdint>

#define DM 1024
#define NH 16
#define DH 64
#define BB 2
#define TT 2048
#define MT (BB*TT)    // 4096 rows total
#define CH 128        // chunk size
#define NC (TT/CH)    // 16 chunks

// ---- scratch (no allocations allowed) ----
__device__ float g_q[MT*DM];
__device__ float g_k[MT*DM];
__device__ float g_v[MT*DM];
__device__ float g_y[MT*DM];
__device__ float g_yn[MT*DM];
__device__ float g_stats[BB*NH*2];
__device__ float g_P[BB*NH*NC*DH*DH];
__device__ float g_S[BB*NH*NC*DH*DH];
__device__ __nv_bfloat16 g_ah[MT*DM];     // activation hi
__device__ __nv_bfloat16 g_al[MT*DM];     // activation lo
__device__ __nv_bfloat16 g_wh[4*DM*DM];   // weight hi (q,k,v,o)
__device__ __nv_bfloat16 g_wl[4*DM*DM];   // weight lo

// ============================================================
// helpers
// ============================================================
__device__ __forceinline__ uint32_t smem_u32(const void* p) {
    uint32_t a;
    asm("{ .reg .u64 t; cvta.to.shared.u64 t, %1; cvt.u32.u64 %0, t; }" : "=r"(a) : "l"(p));
    return a;
}

#define CP16(smem_addr, gptr) \
    asm volatile("cp.async.cg.shared.global [%0], [%1], 16;" :: "r"(smem_addr), "l"(gptr))

__device__ __forceinline__ void ldmx4(uint32_t* r, uint32_t addr) {
    asm volatile("ldmatrix.sync.aligned.m8n8.x4.shared.b16 {%0,%1,%2,%3}, [%4];"
        : "=r"(r[0]), "=r"(r[1]), "=r"(r[2]), "=r"(r[3]) : "r"(addr));
}

__device__ __forceinline__ void mma16816(float* d, const uint32_t* a, uint32_t b0, uint32_t b1) {
    asm volatile("mma.sync.aligned.m16n8k16.row.col.f32.bf16.bf16.f32 "
        "{%0,%1,%2,%3}, {%4,%5,%6,%7}, {%8,%9}, {%0,%1,%2,%3};"
        : "+f"(d[0]), "+f"(d[1]), "+f"(d[2]), "+f"(d[3])
        : "r"(a[0]), "r"(a[1]), "r"(a[2]), "r"(a[3]), "r"(b0), "r"(b1));
}

// ============================================================
// split: hi = bf16(x), lo = bf16(x - hi)
// ============================================================
__global__ void split_bf16(const float* __restrict__ in, __nv_bfloat16* __restrict__ hi,
                           __nv_bfloat16* __restrict__ lo, int n4)
{
    int i = blockIdx.x * blockDim.x + threadIdx.x;
    if (i >= n4) return;
    float4 x = *(const float4*)(in + (size_t)i * 4);
    __nv_bfloat16 h0 = __float2bfloat16(x.x), h1 = __float2bfloat16(x.y);
    __nv_bfloat16 h2 = __float2bfloat16(x.z), h3 = __float2bfloat16(x.w);
    __nv_bfloat16 l0 = __float2bfloat16(x.x - __bfloat162float(h0));
    __nv_bfloat16 l1 = __float2bfloat16(x.y - __bfloat162float(h1));
    __nv_bfloat16 l2 = __float2bfloat16(x.z - __bfloat162float(h2));
    __nv_bfloat16 l3 = __float2bfloat16(x.w - __bfloat162float(h3));
    __nv_bfloat162* hp = (__nv_bfloat162*)(hi + (size_t)i * 4);
    __nv_bfloat162* lp = (__nv_bfloat162*)(lo + (size_t)i * 4);
    hp[0] = __nv_bfloat162(h0, h1); hp[1] = __nv_bfloat162(h2, h3);
    lp[0] = __nv_bfloat162(l0, l1); lp[1] = __nv_bfloat162(l2, l3);
}

// ============================================================
// HMMA bf16 GEMM with Ootomo split: C[M,N] = A[M,K] @ B[N,K]^T
// 128x128x32 block tile, 8 warps (2x4), warp tile 64x32, cp.async x2 stages
// smem halves: stage stride 20480, arrays stride 5120, row stride 40 (pad 8)
// ============================================================
#define GSM_BYTES (2*4*128*40*2)   // 81920

__global__ __launch_bounds__(256)
void gemm_mma(const __nv_bfloat16* __restrict__ Ah, const __nv_bfloat16* __restrict__ Al,
              const __nv_bfloat16* __restrict__ Bh, const __nv_bfloat16* __restrict__ Bl,
              float* __restrict__ C, int M, int N, int K)
{
    extern __shared__ __nv_bfloat16 smh[];
    const uint32_t sbase = smem_u32(smh);
    const int tid = threadIdx.x;
    const int lane = tid & 31;
    const int w = tid >> 5;
    const int wr = w >> 2;          // 0..1  (m)
    const int wc = w & 3;           // 0..3  (n)
    const int m0 = blockIdx.y * 128;
    const int n0 = blockIdx.x * 128;

    const int lrow = tid >> 2;      // 0..63
    const int lc16 = tid & 3;

    const __nv_bfloat16* gsrc[4] = {Ah, Al, Bh, Bl};

    float acc[4][4][4];
    #pragma unroll
    for (int m = 0; m < 4; m++)
        #pragma unroll
        for (int n = 0; n < 4; n++)
            #pragma unroll
            for (int e = 0; e < 4; e++) acc[m][n][e] = 0.f;

    const int NCH = K >> 5;   // 32

    auto load_stage = [&](int s, int k0) {
        uint32_t sb = sbase + (uint32_t)s * 20480u * 2u;
        #pragma unroll
        for (int arr = 0; arr < 4; arr++) {
            const __nv_bfloat16* g = gsrc[arr];
            int base_row = (arr < 2) ? m0 : n0;
            #pragma unroll
            for (int half = 0; half < 2; half++) {
                int row = lrow + half * 64;
                uint32_t so = sb + (uint32_t)(arr * 5120 + row * 40 + lc16 * 8) * 2u;
                const __nv_bfloat16* gp = g + (size_t)(base_row + row) * K + k0 + lc16 * 8;
                CP16(so, gp);
            }
        }
    };

    load_stage(0, 0);
    asm volatile("cp.async.commit_group;" ::: "memory");

    for (int c = 0; c < NCH; ++c) {
        const int s = c & 1;
        if (c + 1 < NCH) {
            load_stage(s ^ 1, (c + 1) << 5);
            asm volatile("cp.async.commit_group;" ::: "memory");
            asm volatile("cp.async.wait_group 1;" ::: "memory");
        } else {
            asm volatile("cp.async.wait_group 0;" ::: "memory");
        }
        __syncthreads();

        const uint32_t sb = sbase + (uint32_t)s * 20480u * 2u;
        const uint32_t sA  = sb;
        const uint32_t sAl = sb + 5120u * 2u;
        const uint32_t sB  = sb + 10240u * 2u;
        const uint32_t sBl = sb + 15360u * 2u;

        #pragma unroll
        for (int kk = 0; kk < 2; ++kk) {
            const int kb = kk * 16;
            uint32_t ah4[4][4], al4[4][4];
            const uint32_t arow = (uint32_t)(wr * 64 + (lane & 15));
            const uint32_t acol = (uint32_t)(kb + (lane >> 4) * 8);
            #pragma unroll
            for (int m = 0; m < 4; m++) {
                uint32_t off = ((arow + m * 16) * 40u + acol) * 2u;
                ldmx4(ah4[m], sA  + off);
                ldmx4(al4[m], sAl + off);
            }
            uint32_t bh4[2][4], bl4[2][4];
            const uint32_t brow = (uint32_t)(wc * 32 + (lane & 7) + ((lane >> 4) << 3));
            const uint32_t bcol = (uint32_t)(kb + ((lane >> 3) & 1) * 8);
            #pragma unroll
            for (int p = 0; p < 2; p++) {
                uint32_t off = ((brow + p * 16) * 40u + bcol) * 2u;
                ldmx4(bh4[p], sB  + off);
                ldmx4(bl4[p], sBl + off);
            }
            #pragma unroll
            for (int m = 0; m < 4; m++) {
                #pragma unroll
                for (int n = 0; n < 4; n++) {
                    uint32_t b0 = bh4[n >> 1][(n & 1) * 2];
                    uint32_t b1 = bh4[n >> 1][(n & 1) * 2 + 1];
                    uint32_t c0 = bl4[n >> 1][(n & 1) * 2];
                    uint32_t c1 = bl4[n >> 1][(n & 1) * 2 + 1];
                    mma16816(acc[m][n], ah4[m], b0, b1);
                    mma16816(acc[m][n], ah4[m], c0, c1);
                    mma16816(acc[m][n], al4[m], b0, b1);
                }
            }
        }
        __syncthreads();
    }

    const int r0 = m0 + wr * 64 + (lane >> 2);
    const int cc = n0 + wc * 32 + (lane & 3) * 2;
    #pragma unroll
    for (int m = 0; m < 4; m++) {
        #pragma unroll
        for (int n = 0; n < 4; n++) {
            float* p0 = C + (size_t)(r0 + m * 16) * N + cc + n * 8;
            float* p1 = C + (size_t)(r0 + m * 16 + 8) * N + cc + n * 8;
            *(float2*)p0 = make_float2(acc[m][n][0], acc[m][n][1]);
            *(float2*)p1 = make_float2(acc[m][n][2], acc[m][n][3]);
        }
    }
}

// ============================================================
// chunk_state
// ============================================================
__global__ __launch_bounds__(256)
void chunk_state(const float* __restrict__ kmat, const float* __restrict__ vmat,
                 float* __restrict__ P)
{
    __shared__ float Ks[CH][68];
    __shared__ float Vs[CH][68];
    const int ch = blockIdx.x;
    const int bh = blockIdx.y;
    const int b = bh >> 4, h = bh & 15;
    const float lg = log2f(1.f - exp2f(-5.f - (float)h));
    const int tid = threadIdx.x;
    const int j0 = ch * CH;

    const float* kbase = kmat + ((size_t)(b*TT + j0))*DM + h*DH;
    const float* vbase = vmat + ((size_t)(b*TT + j0))*DM + h*DH;
    for (int s = tid; s < CH*16; s += 256) {
        int row = s >> 4, c4 = (s & 15) << 2;
        float sc = exp2f(lg * (float)(CH - row));
        float4 kk = *(const float4*)(kbase + (size_t)row*DM + c4);
        Ks[row][c4+0] = kk.x*sc; Ks[row][c4+1] = kk.y*sc;
        Ks[row][c4+2] = kk.z*sc; Ks[row][c4+3] = kk.w*sc;
        float4 vv = *(const float4*)(vbase + (size_t)row*DM + c4);
        *(float4*)&Vs[row][c4] = vv;
    }
    __syncthreads();

    const int tr = tid >> 4, tc = tid & 15;
    float acc[4][4];
    #pragma unroll
    for (int i = 0; i < 4; i++)
        #pragma unroll
        for (int j = 0; j < 4; j++) acc[i][j] = 0.f;

    #pragma unroll 4
    for (int j = 0; j < CH; j++) {
        float ar[4], br[4];
        *(float4*)&ar[0] = *(const float4*)&Ks[j][tr*4];
        *(float4*)&br[0] = *(const float4*)&Vs[j][tc*4];
        #pragma unroll
        for (int i = 0; i < 4; i++)
            #pragma unroll
            for (int jj = 0; jj < 4; jj++)
                acc[i][jj] += ar[i] * br[jj];
    }

    float* pbase = P + ((size_t)(bh*NC + ch))*DH*DH;
    #pragma unroll
    for (int i = 0; i < 4; i++)
        *(float4*)(pbase + (tr*4 + i)*DH + tc*4) =
            make_float4(acc[i][0], acc[i][1], acc[i][2], acc[i][3]);
}

// ============================================================
// state_scan
// ============================================================
__global__ __launch_bounds__(256)
void state_scan(const float* __restrict__ P, float* __restrict__ S)
{
    const int bh = blockIdx.x;
    const int h = bh & 15;
    const float lg = log2f(1.f - exp2f(-5.f - (float)h));
    const float gC = exp2f(lg * (float)CH);
    const int tid = threadIdx.x;

    float s[16];
    #pragma unroll
    for (int r = 0; r < 16; r++) s[r] = 0.f;

    for (int n = 0; n < NC; n++) {
        const size_t base = ((size_t)(bh*NC + n))*DH*DH;
        #pragma unroll
        for (int r = 0; r < 16; r++)
            S[base + tid + 256*r] = s[r] * 0.125f;
        #pragma unroll
        for (int r = 0; r < 16; r++)
            s[r] = gC * s[r] + P[base + tid + 256*r];
    }
}

// ============================================================
// retention_chunk
// ============================================================
#define RET_SMEM_FLOATS (64*132 + 64*68 + 64*68 + 128*68)

__global__ __launch_bounds__(256)
void retention_chunk(const float* __restrict__ q, const float* __restrict__ kmat,
                     const float* __restrict__ vmat, const float* __restrict__ Sg,
                     float* __restrict__ y)
{
    extern __shared__ float smf[];
    float (*QT)[132] = (float (*)[132])smf;
    float (*KT)[68]  = (float (*)[68])(smf + 64*132);
    float (*Vs)[68]  = (float (*)[68])(smf + 64*132 + 64*68);
    float (*Ss)[68]  = (float (*)[68])(smf + 64*132 + 2*64*68);

    const int it = blockIdx.x;
    const int bh = blockIdx.y;
    const int b = bh >> 4, h = bh & 15;
    const int i0 = it * CH;
    const float lg = log2f(1.f - exp2f(-5.f - (float)h));
    const int tid = threadIdx.x;
    const int tr = tid >> 4;
    const int tc = tid & 15;

    const float* qbase = q + ((size_t)(b*TT + i0))*DM + h*DH;
    for (int s = tid; s < CH*16; s += 256) {
        int row = s >> 4, c4 = (s & 15) << 2;
        float4 a = *(const float4*)(qbase + (size_t)row*DM + c4);
        float sc = exp2f(lg * (float)row);
        QT[c4+0][row] = a.x*sc; QT[c4+1][row] = a.y*sc;
        QT[c4+2][row] = a.z*sc; QT[c4+3][row] = a.w*sc;
    }
    const float* sbase = Sg + ((size_t)(bh*NC + it))*DH*DH;
    for (int s = tid; s < 64*16; s += 256) {
        int row = s >> 4, c4 = (s & 15) << 2;
        *(float4*)&KT[row][c4] = *(const float4*)(sbase + row*DH + c4);
    }
    __syncthreads();

    float accy[8][4];
    #pragma unroll
    for (int i = 0; i < 8; i++)
        #pragma unroll
        for (int j = 0; j < 4; j++) accy[i][j] = 0.f;

    #pragma unroll 8
    for (int a = 0; a < DH; a++) {
        float ar[8], br[4];
        *(float4*)&ar[0] = *(const float4*)&QT[a][tr*8];
        *(float4*)&ar[4] = *(const float4*)&QT[a][tr*8+4];
        *(float4*)&br[0] = *(const float4*)&KT[a][tc*4];
        #pragma unroll
        for (int i = 0; i < 8; i++)
            #pragma unroll
            for (int j = 0; j < 4; j++)
                accy[i][j] += ar[i] * br[j];
    }

    #pragma unroll
    for (int jt = 0; jt < 2; jt++) {
        const int j0 = i0 + (jt << 6);
        const int diffbase = -(jt << 6);
        const float* kbase = kmat + ((size_t)(b*TT + j0))*DM + h*DH;
        const float* vbase = vmat + ((size_t)(b*TT + j0))*DM + h*DH;
        __syncthreads();
        for (int s = tid; s < 64*16; s += 256) {
            int row = s >> 4, c4 = (s & 15) << 2;
            float sc = exp2f(-lg * (float)row);
            float4 kk = *(const float4*)(kbase + (size_t)row*DM + c4);
            KT[c4+0][row] = kk.x*sc; KT[c4+1][row] = kk.y*sc;
            KT[c4+2][row] = kk.z*sc; KT[c4+3][row] = kk.w*sc;
            float4 vv = *(const float4*)(vbase + (size_t)row*DM + c4);
            *(float4*)&Vs[row][c4] = vv;
        }
        __syncthreads();

        float acc1[8][4];
        #pragma unroll
        for (int i = 0; i < 8; i++)
            #pragma unroll
            for (int j = 0; j < 4; j++) acc1[i][j] = 0.f;
        #pragma unroll 8
        for (int c = 0; c < DH; c++) {
            float ar[8], br[4];
            *(float4*)&ar[0] = *(const float4*)&QT[c][tr*8];
            *(float4*)&ar[4] = *(const float4*)&QT[c][tr*8+4];
            *(float4*)&br[0] = *(const float4*)&KT[c][tc*4];
            #pragma unroll
            for (int i = 0; i < 8; i++)
                #pragma unroll
                for (int j = 0; j < 4; j++)
                    acc1[i][j] += ar[i] * br[j];
        }

        const float base = exp2f(lg * (float)diffbase) * 0.125f;
        #pragma unroll
        for (int i = 0; i < 8; i++) {
            const int ir = tr*8 + i;
            float o0 = acc1[i][0]*base, o1 = acc1[i][1]*base;
            float o2 = acc1[i][2]*base, o3 = acc1[i][3]*base;
            int d0 = diffbase + ir - (tc*4);
            if (d0     < 0) o0 = 0.f;
            if (d0 - 1 < 0) o1 = 0.f;
            if (d0 - 2 < 0) o2 = 0.f;
            if (d0 - 3 < 0) o3 = 0.f;
            *(float4*)&Ss[ir][tc*4] = make_float4(o0, o1, o2, o3);
        }
        __syncthreads();

        #pragma unroll 8
        for (int jr = 0; jr < 64; jr++) {
            float br[4];
            *(float4*)&br[0] = *(const float4*)&Vs[jr][tc*4];
            #pragma unroll
            for (int i = 0; i < 8; i++) {
                float sv = Ss[tr*8+i][jr];
                accy[i][0] += sv * br[0];
                accy[i][1] += sv * br[1];
                accy[i][2] += sv * br[2];
                accy[i][3] += sv * br[3];
            }
        }
    }

    float* ybase = y + ((size_t)(b*TT + i0))*DM + h*DH;
    #pragma unroll
    for (int i = 0; i < 8; i++) {
        *(float4*)(ybase + (size_t)(tr*8 + i)*DM + tc*4) =
            make_float4(accy[i][0], accy[i][1], accy[i][2], accy[i][3]);
    }
}

// ============================================================
// GroupNorm
// ============================================================
__global__ void gn_reduce(const float* __restrict__ y, float* __restrict__ stats)
{
    const int bh = blockIdx.x;
    const int b = bh >> 4, h = bh & 15;
    const float* base = y + (size_t)b*TT*DM + h*DH;
    float s = 0.f, s2 = 0.f;
    for (int sl = threadIdx.x; sl < TT*16; sl += blockDim.x) {
        int t = sl >> 4, c4 = (sl & 15) << 2;
        float4 vv = *(const float4*)(base + (size_t)t*DM + c4);
        s  += vv.x + vv.y + vv.z + vv.w;
        s2 += vv.x*vv.x + vv.y*vv.y + vv.z*vv.z + vv.w*vv.w;
    }
    #pragma unroll
    for (int o = 16; o > 0; o >>= 1) {
        s  += __shfl_down_sync(0xffffffffu, s,  o);
        s2 += __shfl_down_sync(0xffffffffu, s2, o);
    }
    __shared__ float rs[32], rs2[32];
    const int wid = threadIdx.x >> 5, lid = threadIdx.x & 31;
    if (lid == 0) { rs[wid] = s; rs2[wid] = s2; }
    __syncthreads();
    if (wid == 0) {
        const int nw = blockDim.x >> 5;
        s  = (lid < nw) ? rs[lid]  : 0.f;
        s2 = (lid < nw) ? rs2[lid] : 0.f;
        #pragma unroll
        for (int o = 16; o > 0; o >>= 1) {
            s  += __shfl_down_sync(0xffffffffu, s,  o);
            s2 += __shfl_down_sync(0xffffffffu, s2, o);
        }
        if (lid == 0) {
            const float invN = 1.f / (float)(TT * DH);
            float mean = s * invN;
            float var = s2 * invN - mean * mean;
            stats[bh*2]   = mean;
            stats[bh*2+1] = rsqrtf(var + 1e-5f);
        }
    }
}

__global__ void gn_apply(const float* __restrict__ y, const float* __restrict__ stats,
                         const float* __restrict__ gw, const float* __restrict__ gb,
                         float* __restrict__ yn)
{
    size_t e = ((size_t)blockIdx.x * blockDim.x + threadIdx.x) * 4;
    int col = (int)(e % DM);
    size_t row = e / DM;
    int b = (int)(row / TT);
    int g = b * 16 + (col >> 6);
    float mean = stats[g*2], rstd = stats[g*2+1];
    float4 vv = *(const float4*)(y + e);
    float4 w4 = *(const float4*)(gw + col);
    float4 b4 = *(const float4*)(gb + col);
    float4 o;
    o.x = (vv.x - mean) * rstd * w4.x + b4.x;
    o.y = (vv.y - mean) * rstd * w4.y + b4.y;
    o.z = (vv.z - mean) * rstd * w4.z + b4.z;
    o.w = (vv.w - mean) * rstd * w4.w + b4.w;
    *(float4*)(yn + e) = o;
}

// ============================================================
extern "C" void kernel_launch(void* const* d_in, const int* in_sizes, int n_in,
                              void* d_out, int out_size)
{
    const float* x  = (const float*)d_in[0];
    const float* Wq = (const float*)d_in[1];
    const float* Wk = (const float*)d_in[2];
    const float* Wv = (const float*)d_in[3];
    const float* Wo = (const float*)d_in[4];
    const float* gw = (const float*)d_in[5];
    const float* gb = (const float*)d_in[6];
    float* out = (float*)d_out;

    float *q, *k, *v, *y, *yn, *st, *P, *S;
    __nv_bfloat16 *ah, *al, *wh, *wl;
    cudaGetSymbolAddress((void**)&q,  g_q);
    cudaGetSymbolAddress((void**)&k,  g_k);
    cudaGetSymbolAddress((void**)&v,  g_v);
    cudaGetSymbolAddress((void**)&y,  g_y);
    cudaGetSymbolAddress((void**)&yn, g_yn);
    cudaGetSymbolAddress((void**)&st, g_stats);
    cudaGetSymbolAddress((void**)&P,  g_P);
    cudaGetSymbolAddress((void**)&S,  g_S);
    cudaGetSymbolAddress((void**)&ah, g_ah);
    cudaGetSymbolAddress((void**)&al, g_al);
    cudaGetSymbolAddress((void**)&wh, g_wh);
    cudaGetSymbolAddress((void**)&wl, g_wl);

    const int ret_smem = RET_SMEM_FLOATS * (int)sizeof(float);
    cudaFuncSetAttribute(retention_chunk, cudaFuncAttributeMaxDynamicSharedMemorySize, ret_smem);
    cudaFuncSetAttribute(gemm_mma, cudaFuncAttributeMaxDynamicSharedMemorySize, GSM_BYTES);

    const int WN = DM * DM;
    split_bf16<<<(MT*DM/4 + 255)/256, 256>>>(x, ah, al, MT*DM/4);
    split_bf16<<<(WN/4 + 255)/256, 256>>>(Wq, wh + 0*WN, wl + 0*WN, WN/4);
    split_bf16<<<(WN/4 + 255)/256, 256>>>(Wk, wh + 1*WN, wl + 1*WN, WN/4);
    split_bf16<<<(WN/4 + 255)/256, 256>>>(Wv, wh + 2*WN, wl + 2*WN, WN/4);
    split_bf16<<<(WN/4 + 255)/256, 256>>>(Wo, wh + 3*WN, wl + 3*WN, WN/4);

    dim3 gg(DM/128, MT/128);   // (8, 32)
    gemm_mma<<<gg, 256, GSM_BYTES>>>(ah, al, wh + 0*WN, wl + 0*WN, q, MT, DM, DM);
    gemm_mma<<<gg, 256, GSM_BYTES>>>(ah, al, wh + 1*WN, wl + 1*WN, k, MT, DM, DM);
    gemm_mma<<<gg, 256, GSM_BYTES>>>(ah, al, wh + 2*WN, wl + 2*WN, v, MT, DM, DM);

    chunk_state<<<dim3(NC, BB*NH), 256>>>(k, v, P);
    state_scan<<<BB*NH, 256>>>(P, S);
    retention_chunk<<<dim3(NC, BB*NH), 256, ret_smem>>>(q, k, v, S, y);

    gn_reduce<<<BB*NH, 512>>>(y, st);
    gn_apply<<<(MT*DM)/(4*256), 256>>>(y, st, gw, gb, yn);

    split_bf16<<<(MT*DM/4 + 255)/256, 256>>>(yn, ah, al, MT*DM/4);
    gemm_mma<<<gg, 256, GSM_BYTES>>>(ah, al, wh + 3*WN, wl + 3*WN, out, MT, DM, DM);
}

// round 6
// speedup vs baseline: 2.8817x; 1.0153x over previous
#include <cuda_runtime.h>
#include <cuda_bf16.h>
#include <cstdint>

#define DM 1024
#define NH 16
#define DH 64
#define BB 2
#define TT 2048
#define MT (BB*TT)    // 4096 rows total
#define CH 128        // chunk size
#define NC (TT/CH)    // 16 chunks

// ---- scratch (no allocations allowed) ----
__device__ float g_q[MT*DM];
__device__ float g_k[MT*DM];
__device__ float g_v[MT*DM];
__device__ float g_y[MT*DM];
__device__ float g_stats[BB*NH*2];
__device__ float g_part[BB*NH*8*2];
__device__ float g_P[BB*NH*NC*DH*DH];
__device__ float g_S[BB*NH*NC*DH*DH];
__device__ __nv_bfloat16 g_ah[MT*DM];     // activation hi
__device__ __nv_bfloat16 g_al[MT*DM];     // activation lo
__device__ __nv_bfloat16 g_wh[4*DM*DM];   // weight hi (q,k,v,o)
__device__ __nv_bfloat16 g_wl[4*DM*DM];   // weight lo

// ============================================================
// helpers
// ============================================================
__device__ __forceinline__ uint32_t smem_u32(const void* p) {
    uint32_t a;
    asm("{ .reg .u64 t; cvta.to.shared.u64 t, %1; cvt.u32.u64 %0, t; }" : "=r"(a) : "l"(p));
    return a;
}

#define CP16(smem_addr, gptr) \
    asm volatile("cp.async.cg.shared.global [%0], [%1], 16;" :: "r"(smem_addr), "l"(gptr))

__device__ __forceinline__ void ldmx4(uint32_t* r, uint32_t addr) {
    asm volatile("ldmatrix.sync.aligned.m8n8.x4.shared.b16 {%0,%1,%2,%3}, [%4];"
        : "=r"(r[0]), "=r"(r[1]), "=r"(r[2]), "=r"(r[3]) : "r"(addr));
}

__device__ __forceinline__ void mma16816(float* d, const uint32_t* a, uint32_t b0, uint32_t b1) {
    asm volatile("mma.sync.aligned.m16n8k16.row.col.f32.bf16.bf16.f32 "
        "{%0,%1,%2,%3}, {%4,%5,%6,%7}, {%8,%9}, {%0,%1,%2,%3};"
        : "+f"(d[0]), "+f"(d[1]), "+f"(d[2]), "+f"(d[3])
        : "r"(a[0]), "r"(a[1]), "r"(a[2]), "r"(a[3]), "r"(b0), "r"(b1));
}

__device__ __forceinline__ void split1(float x, __nv_bfloat16& h, __nv_bfloat16& l) {
    h = __float2bfloat16(x);
    l = __float2bfloat16(x - __bfloat162float(h));
}

// ============================================================
// split: hi = bf16(x), lo = bf16(x - hi)
// ============================================================
__global__ void split_bf16(const float* __restrict__ in, __nv_bfloat16* __restrict__ hi,
                           __nv_bfloat16* __restrict__ lo, int n4)
{
    int i = blockIdx.x * blockDim.x + threadIdx.x;
    if (i >= n4) return;
    float4 x = *(const float4*)(in + (size_t)i * 4);
    __nv_bfloat16 h0, h1, h2, h3, l0, l1, l2, l3;
    split1(x.x, h0, l0); split1(x.y, h1, l1);
    split1(x.z, h2, l2); split1(x.w, h3, l3);
    __nv_bfloat162* hp = (__nv_bfloat162*)(hi + (size_t)i * 4);
    __nv_bfloat162* lp = (__nv_bfloat162*)(lo + (size_t)i * 4);
    hp[0] = __nv_bfloat162(h0, h1); hp[1] = __nv_bfloat162(h2, h3);
    lp[0] = __nv_bfloat162(l0, l1); lp[1] = __nv_bfloat162(l2, l3);
}

// ============================================================
// HMMA bf16 GEMM with Ootomo split; batched over blockIdx.z (QKV).
// 128x128x32 tile, 8 warps, warp tile 64x32, cp.async x2 stages.
// ============================================================
#define GSM_BYTES (2*4*128*40*2)   // 81920

__global__ __launch_bounds__(256)
void gemm_mma(const __nv_bfloat16* __restrict__ Ah, const __nv_bfloat16* __restrict__ Al,
              const __nv_bfloat16* __restrict__ Wh, const __nv_bfloat16* __restrict__ Wl,
              float* __restrict__ C0, float* __restrict__ C1, float* __restrict__ C2,
              int M, int N, int K, int wbase)
{
    extern __shared__ __nv_bfloat16 smh[];
    const uint32_t sbase = smem_u32(smh);
    const int tid = threadIdx.x;
    const int lane = tid & 31;
    const int w = tid >> 5;
    const int wr = w >> 2;
    const int wc = w & 3;
    const int m0 = blockIdx.y * 128;
    const int n0 = blockIdx.x * 128;
    const int z = blockIdx.z;

    float* C = (z == 0) ? C0 : (z == 1) ? C1 : C2;
    const size_t woff = (size_t)(wbase + z) * DM * DM;
    const __nv_bfloat16* Bh = Wh + woff;
    const __nv_bfloat16* Bl = Wl + woff;

    const int lrow = tid >> 2;
    const int lc16 = tid & 3;

    const __nv_bfloat16* gsrc[4] = {Ah, Al, Bh, Bl};

    float acc[4][4][4];
    #pragma unroll
    for (int m = 0; m < 4; m++)
        #pragma unroll
        for (int n = 0; n < 4; n++)
            #pragma unroll
            for (int e = 0; e < 4; e++) acc[m][n][e] = 0.f;

    const int NCH = K >> 5;

    auto load_stage = [&](int s, int k0) {
        uint32_t sb = sbase + (uint32_t)s * 20480u * 2u;
        #pragma unroll
        for (int arr = 0; arr < 4; arr++) {
            const __nv_bfloat16* g = gsrc[arr];
            int base_row = (arr < 2) ? m0 : n0;
            #pragma unroll
            for (int half = 0; half < 2; half++) {
                int row = lrow + half * 64;
                uint32_t so = sb + (uint32_t)(arr * 5120 + row * 40 + lc16 * 8) * 2u;
                const __nv_bfloat16* gp = g + (size_t)(base_row + row) * K + k0 + lc16 * 8;
                CP16(so, gp);
            }
        }
    };

    load_stage(0, 0);
    asm volatile("cp.async.commit_group;" ::: "memory");

    for (int c = 0; c < NCH; ++c) {
        const int s = c & 1;
        if (c + 1 < NCH) {
            load_stage(s ^ 1, (c + 1) << 5);
            asm volatile("cp.async.commit_group;" ::: "memory");
            asm volatile("cp.async.wait_group 1;" ::: "memory");
        } else {
            asm volatile("cp.async.wait_group 0;" ::: "memory");
        }
        __syncthreads();

        const uint32_t sb = sbase + (uint32_t)s * 20480u * 2u;
        const uint32_t sA  = sb;
        const uint32_t sAl = sb + 5120u * 2u;
        const uint32_t sB  = sb + 10240u * 2u;
        const uint32_t sBl = sb + 15360u * 2u;

        #pragma unroll
        for (int kk = 0; kk < 2; ++kk) {
            const int kb = kk * 16;
            uint32_t ah4[4][4], al4[4][4];
            const uint32_t arow = (uint32_t)(wr * 64 + (lane & 15));
            const uint32_t acol = (uint32_t)(kb + (lane >> 4) * 8);
            #pragma unroll
            for (int m = 0; m < 4; m++) {
                uint32_t off = ((arow + m * 16) * 40u + acol) * 2u;
                ldmx4(ah4[m], sA  + off);
                ldmx4(al4[m], sAl + off);
            }
            uint32_t bh4[2][4], bl4[2][4];
            const uint32_t brow = (uint32_t)(wc * 32 + (lane & 7) + ((lane >> 4) << 3));
            const uint32_t bcol = (uint32_t)(kb + ((lane >> 3) & 1) * 8);
            #pragma unroll
            for (int p = 0; p < 2; p++) {
                uint32_t off = ((brow + p * 16) * 40u + bcol) * 2u;
                ldmx4(bh4[p], sB  + off);
                ldmx4(bl4[p], sBl + off);
            }
            #pragma unroll
            for (int m = 0; m < 4; m++) {
                #pragma unroll
                for (int n = 0; n < 4; n++) {
                    uint32_t b0 = bh4[n >> 1][(n & 1) * 2];
                    uint32_t b1 = bh4[n >> 1][(n & 1) * 2 + 1];
                    uint32_t c0 = bl4[n >> 1][(n & 1) * 2];
                    uint32_t c1 = bl4[n >> 1][(n & 1) * 2 + 1];
                    mma16816(acc[m][n], ah4[m], b0, b1);
                    mma16816(acc[m][n], ah4[m], c0, c1);
                    mma16816(acc[m][n], al4[m], b0, b1);
                }
            }
        }
        __syncthreads();
    }

    const int r0 = m0 + wr * 64 + (lane >> 2);
    const int cc = n0 + wc * 32 + (lane & 3) * 2;
    #pragma unroll
    for (int m = 0; m < 4; m++) {
        #pragma unroll
        for (int n = 0; n < 4; n++) {
            float* p0 = C + (size_t)(r0 + m * 16) * N + cc + n * 8;
            float* p1 = C + (size_t)(r0 + m * 16 + 8) * N + cc + n * 8;
            *(float2*)p0 = make_float2(acc[m][n][0], acc[m][n][1]);
            *(float2*)p1 = make_float2(acc[m][n][2], acc[m][n][3]);
        }
    }
}

// ============================================================
// chunk_state
// ============================================================
__global__ __launch_bounds__(256)
void chunk_state(const float* __restrict__ kmat, const float* __restrict__ vmat,
                 float* __restrict__ P)
{
    __shared__ float Ks[CH][68];
    __shared__ float Vs[CH][68];
    const int ch = blockIdx.x;
    const int bh = blockIdx.y;
    const int b = bh >> 4, h = bh & 15;
    const float lg = log2f(1.f - exp2f(-5.f - (float)h));
    const int tid = threadIdx.x;
    const int j0 = ch * CH;

    const float* kbase = kmat + ((size_t)(b*TT + j0))*DM + h*DH;
    const float* vbase = vmat + ((size_t)(b*TT + j0))*DM + h*DH;
    for (int s = tid; s < CH*16; s += 256) {
        int row = s >> 4, c4 = (s & 15) << 2;
        float sc = exp2f(lg * (float)(CH - row));
        float4 kk = *(const float4*)(kbase + (size_t)row*DM + c4);
        Ks[row][c4+0] = kk.x*sc; Ks[row][c4+1] = kk.y*sc;
        Ks[row][c4+2] = kk.z*sc; Ks[row][c4+3] = kk.w*sc;
        float4 vv = *(const float4*)(vbase + (size_t)row*DM + c4);
        *(float4*)&Vs[row][c4] = vv;
    }
    __syncthreads();

    const int tr = tid >> 4, tc = tid & 15;
    float acc[4][4];
    #pragma unroll
    for (int i = 0; i < 4; i++)
        #pragma unroll
        for (int j = 0; j < 4; j++) acc[i][j] = 0.f;

    #pragma unroll 4
    for (int j = 0; j < CH; j++) {
        float ar[4], br[4];
        *(float4*)&ar[0] = *(const float4*)&Ks[j][tr*4];
        *(float4*)&br[0] = *(const float4*)&Vs[j][tc*4];
        #pragma unroll
        for (int i = 0; i < 4; i++)
            #pragma unroll
            for (int jj = 0; jj < 4; jj++)
                acc[i][jj] += ar[i] * br[jj];
    }

    float* pbase = P + ((size_t)(bh*NC + ch))*DH*DH;
    #pragma unroll
    for (int i = 0; i < 4; i++)
        *(float4*)(pbase + (tr*4 + i)*DH + tc*4) =
            make_float4(acc[i][0], acc[i][1], acc[i][2], acc[i][3]);
}

// ============================================================
// state_scan
// ============================================================
__global__ __launch_bounds__(256)
void state_scan(const float* __restrict__ P, float* __restrict__ S)
{
    const int bh = blockIdx.x;
    const int h = bh & 15;
    const float lg = log2f(1.f - exp2f(-5.f - (float)h));
    const float gC = exp2f(lg * (float)CH);
    const int tid = threadIdx.x;

    float s[16];
    #pragma unroll
    for (int r = 0; r < 16; r++) s[r] = 0.f;

    for (int n = 0; n < NC; n++) {
        const size_t base = ((size_t)(bh*NC + n))*DH*DH;
        #pragma unroll
        for (int r = 0; r < 16; r++)
            S[base + tid + 256*r] = s[r] * 0.125f;
        #pragma unroll
        for (int r = 0; r < 16; r++)
            s[r] = gC * s[r] + P[base + tid + 256*r];
    }
}

// ============================================================
// retention_chunk
// ============================================================
#define RET_SMEM_FLOATS (64*132 + 64*68 + 64*68 + 128*68)

__global__ __launch_bounds__(256)
void retention_chunk(const float* __restrict__ q, const float* __restrict__ kmat,
                     const float* __restrict__ vmat, const float* __restrict__ Sg,
                     float* __restrict__ y)
{
    extern __shared__ float smf[];
    float (*QT)[132] = (float (*)[132])smf;
    float (*KT)[68]  = (float (*)[68])(smf + 64*132);
    float (*Vs)[68]  = (float (*)[68])(smf + 64*132 + 64*68);
    float (*Ss)[68]  = (float (*)[68])(smf + 64*132 + 2*64*68);

    const int it = blockIdx.x;
    const int bh = blockIdx.y;
    const int b = bh >> 4, h = bh & 15;
    const int i0 = it * CH;
    const float lg = log2f(1.f - exp2f(-5.f - (float)h));
    const int tid = threadIdx.x;
    const int tr = tid >> 4;
    const int tc = tid & 15;

    const float* qbase = q + ((size_t)(b*TT + i0))*DM + h*DH;
    for (int s = tid; s < CH*16; s += 256) {
        int row = s >> 4, c4 = (s & 15) << 2;
        float4 a = *(const float4*)(qbase + (size_t)row*DM + c4);
        float sc = exp2f(lg * (float)row);
        QT[c4+0][row] = a.x*sc; QT[c4+1][row] = a.y*sc;
        QT[c4+2][row] = a.z*sc; QT[c4+3][row] = a.w*sc;
    }
    const float* sbase = Sg + ((size_t)(bh*NC + it))*DH*DH;
    for (int s = tid; s < 64*16; s += 256) {
        int row = s >> 4, c4 = (s & 15) << 2;
        *(float4*)&KT[row][c4] = *(const float4*)(sbase + row*DH + c4);
    }
    __syncthreads();

    float accy[8][4];
    #pragma unroll
    for (int i = 0; i < 8; i++)
        #pragma unroll
        for (int j = 0; j < 4; j++) accy[i][j] = 0.f;

    #pragma unroll 8
    for (int a = 0; a < DH; a++) {
        float ar[8], br[4];
        *(float4*)&ar[0] = *(const float4*)&QT[a][tr*8];
        *(float4*)&ar[4] = *(const float4*)&QT[a][tr*8+4];
        *(float4*)&br[0] = *(const float4*)&KT[a][tc*4];
        #pragma unroll
        for (int i = 0; i < 8; i++)
            #pragma unroll
            for (int j = 0; j < 4; j++)
                accy[i][j] += ar[i] * br[j];
    }

    #pragma unroll
    for (int jt = 0; jt < 2; jt++) {
        const int j0 = i0 + (jt << 6);
        const int diffbase = -(jt << 6);
        const float* kbase = kmat + ((size_t)(b*TT + j0))*DM + h*DH;
        const float* vbase = vmat + ((size_t)(b*TT + j0))*DM + h*DH;
        __syncthreads();
        for (int s = tid; s < 64*16; s += 256) {
            int row = s >> 4, c4 = (s & 15) << 2;
            float sc = exp2f(-lg * (float)row);
            float4 kk = *(const float4*)(kbase + (size_t)row*DM + c4);
            KT[c4+0][row] = kk.x*sc; KT[c4+1][row] = kk.y*sc;
            KT[c4+2][row] = kk.z*sc; KT[c4+3][row] = kk.w*sc;
            float4 vv = *(const float4*)(vbase + (size_t)row*DM + c4);
            *(float4*)&Vs[row][c4] = vv;
        }
        __syncthreads();

        float acc1[8][4];
        #pragma unroll
        for (int i = 0; i < 8; i++)
            #pragma unroll
            for (int j = 0; j < 4; j++) acc1[i][j] = 0.f;
        #pragma unroll 8
        for (int c = 0; c < DH; c++) {
            float ar[8], br[4];
            *(float4*)&ar[0] = *(const float4*)&QT[c][tr*8];
            *(float4*)&ar[4] = *(const float4*)&QT[c][tr*8+4];
            *(float4*)&br[0] = *(const float4*)&KT[c][tc*4];
            #pragma unroll
            for (int i = 0; i < 8; i++)
                #pragma unroll
                for (int j = 0; j < 4; j++)
                    acc1[i][j] += ar[i] * br[j];
        }

        const float base = exp2f(lg * (float)diffbase) * 0.125f;
        #pragma unroll
        for (int i = 0; i < 8; i++) {
            const int ir = tr*8 + i;
            float o0 = acc1[i][0]*base, o1 = acc1[i][1]*base;
            float o2 = acc1[i][2]*base, o3 = acc1[i][3]*base;
            int d0 = diffbase + ir - (tc*4);
            if (d0     < 0) o0 = 0.f;
            if (d0 - 1 < 0) o1 = 0.f;
            if (d0 - 2 < 0) o2 = 0.f;
            if (d0 - 3 < 0) o3 = 0.f;
            *(float4*)&Ss[ir][tc*4] = make_float4(o0, o1, o2, o3);
        }
        __syncthreads();

        #pragma unroll 8
        for (int jr = 0; jr < 64; jr++) {
            float br[4];
            *(float4*)&br[0] = *(const float4*)&Vs[jr][tc*4];
            #pragma unroll
            for (int i = 0; i < 8; i++) {
                float sv = Ss[tr*8+i][jr];
                accy[i][0] += sv * br[0];
                accy[i][1] += sv * br[1];
                accy[i][2] += sv * br[2];
                accy[i][3] += sv * br[3];
            }
        }
    }

    float* ybase = y + ((size_t)(b*TT + i0))*DM + h*DH;
    #pragma unroll
    for (int i = 0; i < 8; i++) {
        *(float4*)(ybase + (size_t)(tr*8 + i)*DM + tc*4) =
            make_float4(accy[i][0], accy[i][1], accy[i][2], accy[i][3]);
    }
}

// ============================================================
// GroupNorm: two-phase reduce + fused apply+split
// ============================================================
__global__ void gn_reduce1(const float* __restrict__ y, float* __restrict__ part)
{
    const int bh = blockIdx.x;       // 0..31
    const int slab = blockIdx.y;     // 0..7
    const int b = bh >> 4, h = bh & 15;
    const float* base = y + (size_t)b*TT*DM + (size_t)slab*(TT/8)*DM + h*DH;
    float s = 0.f, s2 = 0.f;
    for (int sl = threadIdx.x; sl < (TT/8)*16; sl += blockDim.x) {
        int t = sl >> 4, c4 = (sl & 15) << 2;
        float4 vv = *(const float4*)(base + (size_t)t*DM + c4);
        s  += vv.x + vv.y + vv.z + vv.w;
        s2 += vv.x*vv.x + vv.y*vv.y + vv.z*vv.z + vv.w*vv.w;
    }
    #pragma unroll
    for (int o = 16; o > 0; o >>= 1) {
        s  += __shfl_down_sync(0xffffffffu, s,  o);
        s2 += __shfl_down_sync(0xffffffffu, s2, o);
    }
    __shared__ float rs[32], rs2[32];
    const int wid = threadIdx.x >> 5, lid = threadIdx.x & 31;
    if (lid == 0) { rs[wid] = s; rs2[wid] = s2; }
    __syncthreads();
    if (wid == 0) {
        const int nw = blockDim.x >> 5;
        s  = (lid < nw) ? rs[lid]  : 0.f;
        s2 = (lid < nw) ? rs2[lid] : 0.f;
        #pragma unroll
        for (int o = 16; o > 0; o >>= 1) {
            s  += __shfl_down_sync(0xffffffffu, s,  o);
            s2 += __shfl_down_sync(0xffffffffu, s2, o);
        }
        if (lid == 0) {
            part[(bh*8 + slab)*2]   = s;
            part[(bh*8 + slab)*2+1] = s2;
        }
    }
}

__global__ void gn_reduce2(const float* __restrict__ part, float* __restrict__ stats)
{
    const int bh = blockIdx.x;
    if (threadIdx.x == 0) {
        float s = 0.f, s2 = 0.f;
        #pragma unroll
        for (int i = 0; i < 8; i++) {
            s  += part[(bh*8 + i)*2];
            s2 += part[(bh*8 + i)*2+1];
        }
        const float invN = 1.f / (float)(TT * DH);
        float mean = s * invN;
        float var = s2 * invN - mean * mean;
        stats[bh*2]   = mean;
        stats[bh*2+1] = rsqrtf(var + 1e-5f);
    }
}

// fused: yn = (y-mean)*rstd*w+b ; write bf16 split directly
__global__ void gn_apply_split(const float* __restrict__ y, const float* __restrict__ stats,
                               const float* __restrict__ gw, const float* __restrict__ gb,
                               __nv_bfloat16* __restrict__ hi, __nv_bfloat16* __restrict__ lo)
{
    size_t e = ((size_t)blockIdx.x * blockDim.x + threadIdx.x) * 4;
    int col = (int)(e % DM);
    size_t row = e / DM;
    int b = (int)(row / TT);
    int g = b * 16 + (col >> 6);
    float mean = stats[g*2], rstd = stats[g*2+1];
    float4 vv = *(const float4*)(y + e);
    float4 w4 = *(const float4*)(gw + col);
    float4 b4 = *(const float4*)(gb + col);
    float o0 = (vv.x - mean) * rstd * w4.x + b4.x;
    float o1 = (vv.y - mean) * rstd * w4.y + b4.y;
    float o2 = (vv.z - mean) * rstd * w4.z + b4.z;
    float o3 = (vv.w - mean) * rstd * w4.w + b4.w;
    __nv_bfloat16 h0, h1, h2, h3, l0, l1, l2, l3;
    split1(o0, h0, l0); split1(o1, h1, l1);
    split1(o2, h2, l2); split1(o3, h3, l3);
    __nv_bfloat162* hp = (__nv_bfloat162*)(hi + e);
    __nv_bfloat162* lp = (__nv_bfloat162*)(lo + e);
    hp[0] = __nv_bfloat162(h0, h1); hp[1] = __nv_bfloat162(h2, h3);
    lp[0] = __nv_bfloat162(l0, l1); lp[1] = __nv_bfloat162(l2, l3);
}

// ============================================================
extern "C" void kernel_launch(void* const* d_in, const int* in_sizes, int n_in,
                              void* d_out, int out_size)
{
    const float* x  = (const float*)d_in[0];
    const float* Wq = (const float*)d_in[1];
    const float* Wk = (const float*)d_in[2];
    const float* Wv = (const float*)d_in[3];
    const float* Wo = (const float*)d_in[4];
    const float* gw = (const float*)d_in[5];
    const float* gb = (const float*)d_in[6];
    float* out = (float*)d_out;

    float *q, *k, *v, *y, *st, *pt, *P, *S;
    __nv_bfloat16 *ah, *al, *wh, *wl;
    cudaGetSymbolAddress((void**)&q,  g_q);
    cudaGetSymbolAddress((void**)&k,  g_k);
    cudaGetSymbolAddress((void**)&v,  g_v);
    cudaGetSymbolAddress((void**)&y,  g_y);
    cudaGetSymbolAddress((void**)&st, g_stats);
    cudaGetSymbolAddress((void**)&pt, g_part);
    cudaGetSymbolAddress((void**)&P,  g_P);
    cudaGetSymbolAddress((void**)&S,  g_S);
    cudaGetSymbolAddress((void**)&ah, g_ah);
    cudaGetSymbolAddress((void**)&al, g_al);
    cudaGetSymbolAddress((void**)&wh, g_wh);
    cudaGetSymbolAddress((void**)&wl, g_wl);

    const int ret_smem = RET_SMEM_FLOATS * (int)sizeof(float);
    cudaFuncSetAttribute(retention_chunk, cudaFuncAttributeMaxDynamicSharedMemorySize, ret_smem);
    cudaFuncSetAttribute(gemm_mma, cudaFuncAttributeMaxDynamicSharedMemorySize, GSM_BYTES);

    const int WN = DM * DM;
    // split activations + all 4 weights (Wq,Wk,Wv,Wo are contiguous args; split each)
    split_bf16<<<(MT*DM/4 + 255)/256, 256>>>(x, ah, al, MT*DM/4);
    split_bf16<<<(WN/4 + 255)/256, 256>>>(Wq, wh + 0*WN, wl + 0*WN, WN/4);
    split_bf16<<<(WN/4 + 255)/256, 256>>>(Wk, wh + 1*WN, wl + 1*WN, WN/4);
    split_bf16<<<(WN/4 + 255)/256, 256>>>(Wv, wh + 2*WN, wl + 2*WN, WN/4);
    split_bf16<<<(WN/4 + 255)/256, 256>>>(Wo, wh + 3*WN, wl + 3*WN, WN/4);

    // batched QKV GEMM: grid z=3
    dim3 gq(DM/128, MT/128, 3);
    gemm_mma<<<gq, 256, GSM_BYTES>>>(ah, al, wh, wl, q, k, v, MT, DM, DM, 0);

    chunk_state<<<dim3(NC, BB*NH), 256>>>(k, v, P);
    state_scan<<<BB*NH, 256>>>(P, S);
    retention_chunk<<<dim3(NC, BB*NH), 256, ret_smem>>>(q, k, v, S, y);

    gn_reduce1<<<dim3(BB*NH, 8), 512>>>(y, pt);
    gn_reduce2<<<BB*NH, 32>>>(pt, st);
    gn_apply_split<<<(MT*DM)/(4*256), 256>>>(y, st, gw, gb, ah, al);

    // output GEMM (z=1 batch, weight index 3)
    dim3 go(DM/128, MT/128, 1);
    gemm_mma<<<go, 256, GSM_BYTES>>>(ah, al, wh, wl, out, out, out, MT, DM, DM, 3);
}

// round 8
// speedup vs baseline: 3.1969x; 1.1094x over previous
#include <cuda_runtime.h>
#include <cuda_bf16.h>
#include <cstdint>

#define DM 1024
#define NH 16
#define DH 64
#define BB 2
#define TT 2048
#define MT (BB*TT)    // 4096 rows total
#define CH 128        // chunk size
#define NC (TT/CH)    // 16 chunks

// ---- scratch (no allocations allowed) ----
__device__ float g_q[MT*DM];
__device__ float g_k[MT*DM];
__device__ float g_v[MT*DM];
__device__ float g_y[MT*DM];
__device__ float g_stats[BB*NH*2];
__device__ float g_part[BB*NH*8*2];
__device__ float g_P2[BB*NH*NC*2*DH*DH];  // split-K partial states (2 halves)
__device__ float g_S[BB*NH*NC*DH*DH];
__device__ __nv_bfloat16 g_ah[MT*DM];     // activation hi
__device__ __nv_bfloat16 g_al[MT*DM];     // activation lo
__device__ __nv_bfloat16 g_wh[4*DM*DM];   // weight hi (q,k,v,o)
__device__ __nv_bfloat16 g_wl[4*DM*DM];   // weight lo

// ============================================================
// helpers
// ============================================================
__device__ __forceinline__ uint32_t smem_u32(const void* p) {
    uint32_t a;
    asm("{ .reg .u64 t; cvta.to.shared.u64 t, %1; cvt.u32.u64 %0, t; }" : "=r"(a) : "l"(p));
    return a;
}

#define CP16(smem_addr, gptr) \
    asm volatile("cp.async.cg.shared.global [%0], [%1], 16;" :: "r"(smem_addr), "l"(gptr))

__device__ __forceinline__ void ldmx4(uint32_t* r, uint32_t addr) {
    asm volatile("ldmatrix.sync.aligned.m8n8.x4.shared.b16 {%0,%1,%2,%3}, [%4];"
        : "=r"(r[0]), "=r"(r[1]), "=r"(r[2]), "=r"(r[3]) : "r"(addr));
}

__device__ __forceinline__ void mma16816(float* d, const uint32_t* a, uint32_t b0, uint32_t b1) {
    asm volatile("mma.sync.aligned.m16n8k16.row.col.f32.bf16.bf16.f32 "
        "{%0,%1,%2,%3}, {%4,%5,%6,%7}, {%8,%9}, {%0,%1,%2,%3};"
        : "+f"(d[0]), "+f"(d[1]), "+f"(d[2]), "+f"(d[3])
        : "r"(a[0]), "r"(a[1]), "r"(a[2]), "r"(a[3]), "r"(b0), "r"(b1));
}

__device__ __forceinline__ void split1(float x, __nv_bfloat16& h, __nv_bfloat16& l) {
    h = __float2bfloat16(x);
    l = __float2bfloat16(x - __bfloat162float(h));
}

// ============================================================
// merged split: one launch covers x (4 quarters) + 4 weights.
// grid (1024, 8): y=0..3 -> x quarter y ; y=4..7 -> weight y-4
// each (y) region = 256K float4 quads
// ============================================================
__global__ void split_all(const float* __restrict__ x,
                          const float* __restrict__ Wq, const float* __restrict__ Wk,
                          const float* __restrict__ Wv, const float* __restrict__ Wo,
                          __nv_bfloat16* __restrict__ ah, __nv_bfloat16* __restrict__ al,
                          __nv_bfloat16* __restrict__ wh, __nv_bfloat16* __restrict__ wl)
{
    const int yy = blockIdx.y;
    const size_t i = (size_t)blockIdx.x * blockDim.x + threadIdx.x;   // 0..262143
    const size_t e = i * 4;                                           // elem offset in region
    const float* src;
    __nv_bfloat16 *hp, *lp;
    if (yy < 4) {
        src = x  + (size_t)yy * (MT*DM/4) + e;
        hp  = g_ah + (size_t)yy * (MT*DM/4) + e;
        lp  = g_al + (size_t)yy * (MT*DM/4) + e;
    } else {
        const float* ws[4] = {Wq, Wk, Wv, Wo};
        src = ws[yy-4] + e;
        hp  = wh + (size_t)(yy-4) * DM*DM + e;
        lp  = wl + (size_t)(yy-4) * DM*DM + e;
    }
    float4 xx = *(const float4*)src;
    __nv_bfloat16 h0, h1, h2, h3, l0, l1, l2, l3;
    split1(xx.x, h0, l0); split1(xx.y, h1, l1);
    split1(xx.z, h2, l2); split1(xx.w, h3, l3);
    ((__nv_bfloat162*)hp)[0] = __nv_bfloat162(h0, h1);
    ((__nv_bfloat162*)hp)[1] = __nv_bfloat162(h2, h3);
    ((__nv_bfloat162*)lp)[0] = __nv_bfloat162(l0, l1);
    ((__nv_bfloat162*)lp)[1] = __nv_bfloat162(l2, l3);
}

// ============================================================
// HMMA bf16 GEMM with Ootomo split; batched over blockIdx.z.
// ============================================================
#define GSM_BYTES (2*4*128*40*2)   // 81920

__global__ __launch_bounds__(256, 2)
void gemm_mma(const __nv_bfloat16* __restrict__ Ah, const __nv_bfloat16* __restrict__ Al,
              const __nv_bfloat16* __restrict__ Wh, const __nv_bfloat16* __restrict__ Wl,
              float* __restrict__ C0, float* __restrict__ C1, float* __restrict__ C2,
              int M, int N, int K, int wbase)
{
    extern __shared__ __nv_bfloat16 smh[];
    const uint32_t sbase = smem_u32(smh);
    const int tid = threadIdx.x;
    const int lane = tid & 31;
    const int w = tid >> 5;
    const int wr = w >> 2;
    const int wc = w & 3;
    const int m0 = blockIdx.y * 128;
    const int n0 = blockIdx.x * 128;
    const int z = blockIdx.z;

    float* C = (z == 0) ? C0 : (z == 1) ? C1 : C2;
    const size_t woff = (size_t)(wbase + z) * DM * DM;
    const __nv_bfloat16* Bh = Wh + woff;
    const __nv_bfloat16* Bl = Wl + woff;

    const int lrow = tid >> 2;
    const int lc16 = tid & 3;

    const __nv_bfloat16* gsrc[4] = {Ah, Al, Bh, Bl};

    float acc[4][4][4];
    #pragma unroll
    for (int m = 0; m < 4; m++)
        #pragma unroll
        for (int n = 0; n < 4; n++)
            #pragma unroll
            for (int e = 0; e < 4; e++) acc[m][n][e] = 0.f;

    const int NCH = K >> 5;

    auto load_stage = [&](int s, int k0) {
        uint32_t sb = sbase + (uint32_t)s * 20480u * 2u;
        #pragma unroll
        for (int arr = 0; arr < 4; arr++) {
            const __nv_bfloat16* g = gsrc[arr];
            int base_row = (arr < 2) ? m0 : n0;
            #pragma unroll
            for (int half = 0; half < 2; half++) {
                int row = lrow + half * 64;
                uint32_t so = sb + (uint32_t)(arr * 5120 + row * 40 + lc16 * 8) * 2u;
                const __nv_bfloat16* gp = g + (size_t)(base_row + row) * K + k0 + lc16 * 8;
                CP16(so, gp);
            }
        }
    };

    load_stage(0, 0);
    asm volatile("cp.async.commit_group;" ::: "memory");

    for (int c = 0; c < NCH; ++c) {
        const int s = c & 1;
        if (c + 1 < NCH) {
            load_stage(s ^ 1, (c + 1) << 5);
            asm volatile("cp.async.commit_group;" ::: "memory");
            asm volatile("cp.async.wait_group 1;" ::: "memory");
        } else {
            asm volatile("cp.async.wait_group 0;" ::: "memory");
        }
        __syncthreads();

        const uint32_t sb = sbase + (uint32_t)s * 20480u * 2u;
        const uint32_t sA  = sb;
        const uint32_t sAl = sb + 5120u * 2u;
        const uint32_t sB  = sb + 10240u * 2u;
        const uint32_t sBl = sb + 15360u * 2u;

        #pragma unroll
        for (int kk = 0; kk < 2; ++kk) {
            const int kb = kk * 16;
            uint32_t ah4[4][4], al4[4][4];
            const uint32_t arow = (uint32_t)(wr * 64 + (lane & 15));
            const uint32_t acol = (uint32_t)(kb + (lane >> 4) * 8);
            #pragma unroll
            for (int m = 0; m < 4; m++) {
                uint32_t off = ((arow + m * 16) * 40u + acol) * 2u;
                ldmx4(ah4[m], sA  + off);
                ldmx4(al4[m], sAl + off);
            }
            uint32_t bh4[2][4], bl4[2][4];
            const uint32_t brow = (uint32_t)(wc * 32 + (lane & 7) + ((lane >> 4) << 3));
            const uint32_t bcol = (uint32_t)(kb + ((lane >> 3) & 1) * 8);
            #pragma unroll
            for (int p = 0; p < 2; p++) {
                uint32_t off = ((brow + p * 16) * 40u + bcol) * 2u;
                ldmx4(bh4[p], sB  + off);
                ldmx4(bl4[p], sBl + off);
            }
            #pragma unroll
            for (int m = 0; m < 4; m++) {
                #pragma unroll
                for (int n = 0; n < 4; n++) {
                    uint32_t b0 = bh4[n >> 1][(n & 1) * 2];
                    uint32_t b1 = bh4[n >> 1][(n & 1) * 2 + 1];
                    uint32_t c0 = bl4[n >> 1][(n & 1) * 2];
                    uint32_t c1 = bl4[n >> 1][(n & 1) * 2 + 1];
                    mma16816(acc[m][n], ah4[m], b0, b1);
                    mma16816(acc[m][n], ah4[m], c0, c1);
                    mma16816(acc[m][n], al4[m], b0, b1);
                }
            }
        }
        __syncthreads();
    }

    const int r0 = m0 + wr * 64 + (lane >> 2);
    const int cc = n0 + wc * 32 + (lane & 3) * 2;
    #pragma unroll
    for (int m = 0; m < 4; m++) {
        #pragma unroll
        for (int n = 0; n < 4; n++) {
            float* p0 = C + (size_t)(r0 + m * 16) * N + cc + n * 8;
            float* p1 = C + (size_t)(r0 + m * 16 + 8) * N + cc + n * 8;
            *(float2*)p0 = make_float2(acc[m][n][0], acc[m][n][1]);
            *(float2*)p1 = make_float2(acc[m][n][2], acc[m][n][3]);
        }
    }
}

// ============================================================
// chunk_state split-K: grid (NC, BH, 2); each block does 64 j-rows
// P2[((bh*NC+ch)*2+z)] = sum_{j in half} gamma^(CH-j) k_j v_j^T
// ============================================================
__global__ __launch_bounds__(256)
void chunk_state(const float* __restrict__ kmat, const float* __restrict__ vmat,
                 float* __restrict__ P2)
{
    __shared__ float Ks[64][68];
    __shared__ float Vs[64][68];
    const int ch = blockIdx.x;
    const int bh = blockIdx.y;
    const int z  = blockIdx.z;
    const int b = bh >> 4, h = bh & 15;
    const float lg = log2f(1.f - exp2f(-5.f - (float)h));
    const int tid = threadIdx.x;
    const int j0 = ch * CH + z * 64;

    const float* kbase = kmat + ((size_t)(b*TT + j0))*DM + h*DH;
    const float* vbase = vmat + ((size_t)(b*TT + j0))*DM + h*DH;
    for (int s = tid; s < 64*16; s += 256) {
        int row = s >> 4, c4 = (s & 15) << 2;
        float sc = exp2f(lg * (float)(CH - z*64 - row));
        float4 kk = *(const float4*)(kbase + (size_t)row*DM + c4);
        Ks[row][c4+0] = kk.x*sc; Ks[row][c4+1] = kk.y*sc;
        Ks[row][c4+2] = kk.z*sc; Ks[row][c4+3] = kk.w*sc;
        float4 vv = *(const float4*)(vbase + (size_t)row*DM + c4);
        *(float4*)&Vs[row][c4] = vv;
    }
    __syncthreads();

    const int tr = tid >> 4, tc = tid & 15;
    float acc[4][4];
    #pragma unroll
    for (int i = 0; i < 4; i++)
        #pragma unroll
        for (int j = 0; j < 4; j++) acc[i][j] = 0.f;

    #pragma unroll 4
    for (int j = 0; j < 64; j++) {
        float ar[4], br[4];
        *(float4*)&ar[0] = *(const float4*)&Ks[j][tr*4];
        *(float4*)&br[0] = *(const float4*)&Vs[j][tc*4];
        #pragma unroll
        for (int i = 0; i < 4; i++)
            #pragma unroll
            for (int jj = 0; jj < 4; jj++)
                acc[i][jj] += ar[i] * br[jj];
    }

    float* pbase = P2 + ((size_t)((bh*NC + ch)*2 + z))*DH*DH;
    #pragma unroll
    for (int i = 0; i < 4; i++)
        *(float4*)(pbase + (tr*4 + i)*DH + tc*4) =
            make_float4(acc[i][0], acc[i][1], acc[i][2], acc[i][3]);
}

// ============================================================
// state_scan: sums the two split-K halves while scanning
// ============================================================
__global__ __launch_bounds__(256)
void state_scan(const float* __restrict__ P2, float* __restrict__ S)
{
    const int bh = blockIdx.x;
    const int h = bh & 15;
    const float lg = log2f(1.f - exp2f(-5.f - (float)h));
    const float gC = exp2f(lg * (float)CH);
    const int tid = threadIdx.x;

    float s[16];
    #pragma unroll
    for (int r = 0; r < 16; r++) s[r] = 0.f;

    for (int n = 0; n < NC; n++) {
        const size_t sb = ((size_t)(bh*NC + n))*DH*DH;
        const size_t pb = ((size_t)(bh*NC + n))*2*DH*DH;
        #pragma unroll
        for (int r = 0; r < 16; r++)
            S[sb + tid + 256*r] = s[r] * 0.125f;
        #pragma unroll
        for (int r = 0; r < 16; r++)
            s[r] = gC * s[r] + P2[pb + tid + 256*r] + P2[pb + DH*DH + tid + 256*r];
    }
}

// ============================================================
// retention_chunk
// ============================================================
#define RET_SMEM_FLOATS (64*132 + 64*68 + 64*68 + 128*68)

__global__ __launch_bounds__(256)
void retention_chunk(const float* __restrict__ q, const float* __restrict__ kmat,
                     const float* __restrict__ vmat, const float* __restrict__ Sg,
                     float* __restrict__ y)
{
    extern __shared__ float smf[];
    float (*QT)[132] = (float (*)[132])smf;
    float (*KT)[68]  = (float (*)[68])(smf + 64*132);
    float (*Vs)[68]  = (float (*)[68])(smf + 64*132 + 64*68);
    float (*Ss)[68]  = (float (*)[68])(smf + 64*132 + 2*64*68);

    const int it = blockIdx.x;
    const int bh = blockIdx.y;
    const int b = bh >> 4, h = bh & 15;
    const int i0 = it * CH;
    const float lg = log2f(1.f - exp2f(-5.f - (float)h));
    const int tid = threadIdx.x;
    const int tr = tid >> 4;
    const int tc = tid & 15;

    const float* qbase = q + ((size_t)(b*TT + i0))*DM + h*DH;
    for (int s = tid; s < CH*16; s += 256) {
        int row = s >> 4, c4 = (s & 15) << 2;
        float4 a = *(const float4*)(qbase + (size_t)row*DM + c4);
        float sc = exp2f(lg * (float)row);
        QT[c4+0][row] = a.x*sc; QT[c4+1][row] = a.y*sc;
        QT[c4+2][row] = a.z*sc; QT[c4+3][row] = a.w*sc;
    }
    const float* sbase = Sg + ((size_t)(bh*NC + it))*DH*DH;
    for (int s = tid; s < 64*16; s += 256) {
        int row = s >> 4, c4 = (s & 15) << 2;
        *(float4*)&KT[row][c4] = *(const float4*)(sbase + row*DH + c4);
    }
    __syncthreads();

    float accy[8][4];
    #pragma unroll
    for (int i = 0; i < 8; i++)
        #pragma unroll
        for (int j = 0; j < 4; j++) accy[i][j] = 0.f;

    #pragma unroll 8
    for (int a = 0; a < DH; a++) {
        float ar[8], br[4];
        *(float4*)&ar[0] = *(const float4*)&QT[a][tr*8];
        *(float4*)&ar[4] = *(const float4*)&QT[a][tr*8+4];
        *(float4*)&br[0] = *(const float4*)&KT[a][tc*4];
        #pragma unroll
        for (int i = 0; i < 8; i++)
            #pragma unroll
            for (int j = 0; j < 4; j++)
                accy[i][j] += ar[i] * br[j];
    }

    #pragma unroll
    for (int jt = 0; jt < 2; jt++) {
        const int j0 = i0 + (jt << 6);
        const int diffbase = -(jt << 6);
        const float* kbase = kmat + ((size_t)(b*TT + j0))*DM + h*DH;
        const float* vbase = vmat + ((size_t)(b*TT + j0))*DM + h*DH;
        __syncthreads();
        for (int s = tid; s < 64*16; s += 256) {
            int row = s >> 4, c4 = (s & 15) << 2;
            float sc = exp2f(-lg * (float)row);
            float4 kk = *(const float4*)(kbase + (size_t)row*DM + c4);
            KT[c4+0][row] = kk.x*sc; KT[c4+1][row] = kk.y*sc;
            KT[c4+2][row] = kk.z*sc; KT[c4+3][row] = kk.w*sc;
            float4 vv = *(const float4*)(vbase + (size_t)row*DM + c4);
            *(float4*)&Vs[row][c4] = vv;
        }
        __syncthreads();

        float acc1[8][4];
        #pragma unroll
        for (int i = 0; i < 8; i++)
            #pragma unroll
            for (int j = 0; j < 4; j++) acc1[i][j] = 0.f;
        #pragma unroll 8
        for (int c = 0; c < DH; c++) {
            float ar[8], br[4];
            *(float4*)&ar[0] = *(const float4*)&QT[c][tr*8];
            *(float4*)&ar[4] = *(const float4*)&QT[c][tr*8+4];
            *(float4*)&br[0] = *(const float4*)&KT[c][tc*4];
            #pragma unroll
            for (int i = 0; i < 8; i++)
                #pragma unroll
                for (int j = 0; j < 4; j++)
                    acc1[i][j] += ar[i] * br[j];
        }

        const float base = exp2f(lg * (float)diffbase) * 0.125f;
        #pragma unroll
        for (int i = 0; i < 8; i++) {
            const int ir = tr*8 + i;
            float o0 = acc1[i][0]*base, o1 = acc1[i][1]*base;
            float o2 = acc1[i][2]*base, o3 = acc1[i][3]*base;
            int d0 = diffbase + ir - (tc*4);
            if (d0     < 0) o0 = 0.f;
            if (d0 - 1 < 0) o1 = 0.f;
            if (d0 - 2 < 0) o2 = 0.f;
            if (d0 - 3 < 0) o3 = 0.f;
            *(float4*)&Ss[ir][tc*4] = make_float4(o0, o1, o2, o3);
        }
        __syncthreads();

        #pragma unroll 8
        for (int jr = 0; jr < 64; jr++) {
            float br[4];
            *(float4*)&br[0] = *(const float4*)&Vs[jr][tc*4];
            #pragma unroll
            for (int i = 0; i < 8; i++) {
                float sv = Ss[tr*8+i][jr];
                accy[i][0] += sv * br[0];
                accy[i][1] += sv * br[1];
                accy[i][2] += sv * br[2];
                accy[i][3] += sv * br[3];
            }
        }
    }

    float* ybase = y + ((size_t)(b*TT + i0))*DM + h*DH;
    #pragma unroll
    for (int i = 0; i < 8; i++) {
        *(float4*)(ybase + (size_t)(tr*8 + i)*DM + tc*4) =
            make_float4(accy[i][0], accy[i][1], accy[i][2], accy[i][3]);
    }
}

// ============================================================
// GroupNorm: two-phase reduce + fused apply+split
// ============================================================
__global__ void gn_reduce1(const float* __restrict__ y, float* __restrict__ part)
{
    const int bh = blockIdx.x;
    const int slab = blockIdx.y;
    const int b = bh >> 4, h = bh & 15;
    const float* base = y + (size_t)b*TT*DM + (size_t)slab*(TT/8)*DM + h*DH;
    float s = 0.f, s2 = 0.f;
    for (int sl = threadIdx.x; sl < (TT/8)*16; sl += blockDim.x) {
        int t = sl >> 4, c4 = (sl & 15) << 2;
        float4 vv = *(const float4*)(base + (size_t)t*DM + c4);
        s  += vv.x + vv.y + vv.z + vv.w;
        s2 += vv.x*vv.x + vv.y*vv.y + vv.z*vv.z + vv.w*vv.w;
    }
    #pragma unroll
    for (int o = 16; o > 0; o >>= 1) {
        s  += __shfl_down_sync(0xffffffffu, s,  o);
        s2 += __shfl_down_sync(0xffffffffu, s2, o);
    }
    __shared__ float rs[32], rs2[32];
    const int wid = threadIdx.x >> 5, lid = threadIdx.x & 31;
    if (lid == 0) { rs[wid] = s; rs2[wid] = s2; }
    __syncthreads();
    if (wid == 0) {
        const int nw = blockDim.x >> 5;
        s  = (lid < nw) ? rs[lid]  : 0.f;
        s2 = (lid < nw) ? rs2[lid] : 0.f;
        #pragma unroll
        for (int o = 16; o > 0; o >>= 1) {
            s  += __shfl_down_sync(0xffffffffu, s,  o);
            s2 += __shfl_down_sync(0xffffffffu, s2, o);
        }
        if (lid == 0) {
            part[(bh*8 + slab)*2]   = s;
            part[(bh*8 + slab)*2+1] = s2;
        }
    }
}

__global__ void gn_reduce2(const float* __restrict__ part, float* __restrict__ stats)
{
    const int bh = blockIdx.x;
    if (threadIdx.x == 0) {
        float s = 0.f, s2 = 0.f;
        #pragma unroll
        for (int i = 0; i < 8; i++) {
            s  += part[(bh*8 + i)*2];
            s2 += part[(bh*8 + i)*2+1];
        }
        const float invN = 1.f / (float)(TT * DH);
        float mean = s * invN;
        float var = s2 * invN - mean * mean;
        stats[bh*2]   = mean;
        stats[bh*2+1] = rsqrtf(var + 1e-5f);
    }
}

__global__ void gn_apply_split(const float* __restrict__ y, const float* __restrict__ stats,
                               const float* __restrict__ gw, const float* __restrict__ gb,
                               __nv_bfloat16* __restrict__ hi, __nv_bfloat16* __restrict__ lo)
{
    size_t e = ((size_t)blockIdx.x * blockDim.x + threadIdx.x) * 4;
    int col = (int)(e % DM);
    size_t row = e / DM;
    int b = (int)(row / TT);
    int g = b * 16 + (col >> 6);
    float mean = stats[g*2], rstd = stats[g*2+1];
    float4 vv = *(const float4*)(y + e);
    float4 w4 = *(const float4*)(gw + col);
    float4 b4 = *(const float4*)(gb + col);
    float o0 = (vv.x - mean) * rstd * w4.x + b4.x;
    float o1 = (vv.y - mean) * rstd * w4.y + b4.y;
    float o2 = (vv.z - mean) * rstd * w4.z + b4.z;
    float o3 = (vv.w - mean) * rstd * w4.w + b4.w;
    __nv_bfloat16 h0, h1, h2, h3, l0, l1, l2, l3;
    split1(o0, h0, l0); split1(o1, h1, l1);
    split1(o2, h2, l2); split1(o3, h3, l3);
    __nv_bfloat162* hp = (__nv_bfloat162*)(hi + e);
    __nv_bfloat162* lp = (__nv_bfloat162*)(lo + e);
    hp[0] = __nv_bfloat162(h0, h1); hp[1] = __nv_bfloat162(h2, h3);
    lp[0] = __nv_bfloat162(l0, l1); lp[1] = __nv_bfloat162(l2, l3);
}

// ============================================================
extern "C" void kernel_launch(void* const* d_in, const int* in_sizes, int n_in,
                              void* d_out, int out_size)
{
    const float* x  = (const float*)d_in[0];
    const float* Wq = (const float*)d_in[1];
    const float* Wk = (const float*)d_in[2];
    const float* Wv = (const float*)d_in[3];
    const float* Wo = (const float*)d_in[4];
    const float* gw = (const float*)d_in[5];
    const float* gb = (const float*)d_in[6];
    float* out = (float*)d_out;

    float *q, *k, *v, *y, *st, *pt, *P2, *S;
    __nv_bfloat16 *ah, *al, *wh, *wl;
    cudaGetSymbolAddress((void**)&q,  g_q);
    cudaGetSymbolAddress((void**)&k,  g_k);
    cudaGetSymbolAddress((void**)&v,  g_v);
    cudaGetSymbolAddress((void**)&y,  g_y);
    cudaGetSymbolAddress((void**)&st, g_stats);
    cudaGetSymbolAddress((void**)&pt, g_part);
    cudaGetSymbolAddress((void**)&P2, g_P2);
    cudaGetSymbolAddress((void**)&S,  g_S);
    cudaGetSymbolAddress((void**)&ah, g_ah);
    cudaGetSymbolAddress((void**)&al, g_al);
    cudaGetSymbolAddress((void**)&wh, g_wh);
    cudaGetSymbolAddress((void**)&wl, g_wl);

    const int ret_smem = RET_SMEM_FLOATS * (int)sizeof(float);
    cudaFuncSetAttribute(retention_chunk, cudaFuncAttributeMaxDynamicSharedMemorySize, ret_smem);
    cudaFuncSetAttribute(gemm_mma, cudaFuncAttributeMaxDynamicSharedMemorySize, GSM_BYTES);

    // one merged split launch (x + 4 weights)
    split_all<<<dim3(1024, 8), 256>>>(x, Wq, Wk, Wv, Wo, ah, al, wh, wl);

    // batched QKV GEMM
    dim3 gq(DM/128, MT/128, 3);
    gemm_mma<<<gq, 256, GSM_BYTES>>>(ah, al, wh, wl, q, k, v, MT, DM, DM, 0);

    chunk_state<<<dim3(NC, BB*NH, 2), 256>>>(k, v, P2);
    state_scan<<<BB*NH, 256>>>(P2, S);
    retention_chunk<<<dim3(NC, BB*NH), 256, ret_smem>>>(q, k, v, S, y);

    gn_reduce1<<<dim3(BB*NH, 8), 512>>>(y, pt);
    gn_reduce2<<<BB*NH, 32>>>(pt, st);
    gn_apply_split<<<(MT*DM)/(4*256), 256>>>(y, st, gw, gb, ah, al);

    // output GEMM (weight index 3)
    dim3 go(DM/128, MT/128, 1);
    gemm_mma<<<go, 256, GSM_BYTES>>>(ah, al, wh, wl, out, out, out, MT, DM, DM, 3);
}

// round 11
// speedup vs baseline: 3.4059x; 1.0654x over previous
#include <cuda_runtime.h>
#include <cuda_bf16.h>
#include <cstdint>

#define DM 1024
#define NH 16
#define DH 64
#define BB 2
#define TT 2048
#define MT (BB*TT)    // 4096 rows total
#define CH 128        // chunk size
#define NC (TT/CH)    // 16 chunks

// ---- scratch (no allocations allowed) ----
__device__ float g_q[MT*DM];
__device__ float g_k[MT*DM];
__device__ float g_v[MT*DM];
__device__ float g_y[MT*DM];
__device__ float g_part[BB*NH*8*2];
__device__ float g_P2[BB*NH*NC*2*DH*DH];  // split-K partial states (2 halves)
__device__ float g_S[BB*NH*NC*DH*DH];
__device__ __nv_bfloat16 g_ah[MT*DM];     // activation hi
__device__ __nv_bfloat16 g_al[MT*DM];     // activation lo
__device__ __nv_bfloat16 g_wh[4*DM*DM];   // weight hi (q,k,v,o)
__device__ __nv_bfloat16 g_wl[4*DM*DM];   // weight lo

// ============================================================
// helpers
// ============================================================
__device__ __forceinline__ uint32_t smem_u32(const void* p) {
    uint32_t a;
    asm("{ .reg .u64 t; cvta.to.shared.u64 t, %1; cvt.u32.u64 %0, t; }" : "=r"(a) : "l"(p));
    return a;
}

#define CP16(smem_addr, gptr) \
    asm volatile("cp.async.cg.shared.global [%0], [%1], 16;" :: "r"(smem_addr), "l"(gptr))

__device__ __forceinline__ void ldmx4(uint32_t* r, uint32_t addr) {
    asm volatile("ldmatrix.sync.aligned.m8n8.x4.shared.b16 {%0,%1,%2,%3}, [%4];"
        : "=r"(r[0]), "=r"(r[1]), "=r"(r[2]), "=r"(r[3]) : "r"(addr));
}

__device__ __forceinline__ void mma16816(float* d, const uint32_t* a, uint32_t b0, uint32_t b1) {
    asm volatile("mma.sync.aligned.m16n8k16.row.col.f32.bf16.bf16.f32 "
        "{%0,%1,%2,%3}, {%4,%5,%6,%7}, {%8,%9}, {%0,%1,%2,%3};"
        : "+f"(d[0]), "+f"(d[1]), "+f"(d[2]), "+f"(d[3])
        : "r"(a[0]), "r"(a[1]), "r"(a[2]), "r"(a[3]), "r"(b0), "r"(b1));
}

__device__ __forceinline__ void split1(float x, __nv_bfloat16& h, __nv_bfloat16& l) {
    h = __float2bfloat16(x);
    l = __float2bfloat16(x - __bfloat162float(h));
}

// ============================================================
// merged split: one launch covers x (4 quarters) + 4 weights.
// ============================================================
__global__ void split_all(const float* __restrict__ x,
                          const float* __restrict__ Wq, const float* __restrict__ Wk,
                          const float* __restrict__ Wv, const float* __restrict__ Wo,
                          __nv_bfloat16* __restrict__ ah, __nv_bfloat16* __restrict__ al,
                          __nv_bfloat16* __restrict__ wh, __nv_bfloat16* __restrict__ wl)
{
    const int yy = blockIdx.y;
    const size_t i = (size_t)blockIdx.x * blockDim.x + threadIdx.x;
    const size_t e = i * 4;
    const float* src;
    __nv_bfloat16 *hp, *lp;
    if (yy < 4) {
        src = x  + (size_t)yy * (MT*DM/4) + e;
        hp  = ah + (size_t)yy * (MT*DM/4) + e;
        lp  = al + (size_t)yy * (MT*DM/4) + e;
    } else {
        const float* ws[4] = {Wq, Wk, Wv, Wo};
        src = ws[yy-4] + e;
        hp  = wh + (size_t)(yy-4) * DM*DM + e;
        lp  = wl + (size_t)(yy-4) * DM*DM + e;
    }
    float4 xx = *(const float4*)src;
    __nv_bfloat16 h0, h1, h2, h3, l0, l1, l2, l3;
    split1(xx.x, h0, l0); split1(xx.y, h1, l1);
    split1(xx.z, h2, l2); split1(xx.w, h3, l3);
    ((__nv_bfloat162*)hp)[0] = __nv_bfloat162(h0, h1);
    ((__nv_bfloat162*)hp)[1] = __nv_bfloat162(h2, h3);
    ((__nv_bfloat162*)lp)[0] = __nv_bfloat162(l0, l1);
    ((__nv_bfloat162*)lp)[1] = __nv_bfloat162(l2, l3);
}

// ============================================================
// HMMA bf16 GEMM with Ootomo split; batched over blockIdx.z.
// ============================================================
#define GSM_BYTES (2*4*128*40*2)   // 81920

__global__ __launch_bounds__(256, 2)
void gemm_mma(const __nv_bfloat16* __restrict__ Ah, const __nv_bfloat16* __restrict__ Al,
              const __nv_bfloat16* __restrict__ Wh, const __nv_bfloat16* __restrict__ Wl,
              float* __restrict__ C0, float* __restrict__ C1, float* __restrict__ C2,
              int M, int N, int K, int wbase)
{
    extern __shared__ __nv_bfloat16 smh[];
    const uint32_t sbase = smem_u32(smh);
    const int tid = threadIdx.x;
    const int lane = tid & 31;
    const int w = tid >> 5;
    const int wr = w >> 2;
    const int wc = w & 3;
    const int m0 = blockIdx.y * 128;
    const int n0 = blockIdx.x * 128;
    const int z = blockIdx.z;

    float* C = (z == 0) ? C0 : (z == 1) ? C1 : C2;
    const size_t woff = (size_t)(wbase + z) * DM * DM;
    const __nv_bfloat16* Bh = Wh + woff;
    const __nv_bfloat16* Bl = Wl + woff;

    const int lrow = tid >> 2;
    const int lc16 = tid & 3;

    const __nv_bfloat16* gsrc[4] = {Ah, Al, Bh, Bl};

    float acc[4][4][4];
    #pragma unroll
    for (int m = 0; m < 4; m++)
        #pragma unroll
        for (int n = 0; n < 4; n++)
            #pragma unroll
            for (int e = 0; e < 4; e++) acc[m][n][e] = 0.f;

    const int NCH = K >> 5;

    auto load_stage = [&](int s, int k0) {
        uint32_t sb = sbase + (uint32_t)s * 20480u * 2u;
        #pragma unroll
        for (int arr = 0; arr < 4; arr++) {
            const __nv_bfloat16* g = gsrc[arr];
            int base_row = (arr < 2) ? m0 : n0;
            #pragma unroll
            for (int half = 0; half < 2; half++) {
                int row = lrow + half * 64;
                uint32_t so = sb + (uint32_t)(arr * 5120 + row * 40 + lc16 * 8) * 2u;
                const __nv_bfloat16* gp = g + (size_t)(base_row + row) * K + k0 + lc16 * 8;
                CP16(so, gp);
            }
        }
    };

    load_stage(0, 0);
    asm volatile("cp.async.commit_group;" ::: "memory");

    for (int c = 0; c < NCH; ++c) {
        const int s = c & 1;
        if (c + 1 < NCH) {
            load_stage(s ^ 1, (c + 1) << 5);
            asm volatile("cp.async.commit_group;" ::: "memory");
            asm volatile("cp.async.wait_group 1;" ::: "memory");
        } else {
            asm volatile("cp.async.wait_group 0;" ::: "memory");
        }
        __syncthreads();

        const uint32_t sb = sbase + (uint32_t)s * 20480u * 2u;
        const uint32_t sA  = sb;
        const uint32_t sAl = sb + 5120u * 2u;
        const uint32_t sB  = sb + 10240u * 2u;
        const uint32_t sBl = sb + 15360u * 2u;

        #pragma unroll
        for (int kk = 0; kk < 2; ++kk) {
            const int kb = kk * 16;
            uint32_t ah4[4][4], al4[4][4];
            const uint32_t arow = (uint32_t)(wr * 64 + (lane & 15));
            const uint32_t acol = (uint32_t)(kb + (lane >> 4) * 8);
            #pragma unroll
            for (int m = 0; m < 4; m++) {
                uint32_t off = ((arow + m * 16) * 40u + acol) * 2u;
                ldmx4(ah4[m], sA  + off);
                ldmx4(al4[m], sAl + off);
            }
            uint32_t bh4[2][4], bl4[2][4];
            const uint32_t brow = (uint32_t)(wc * 32 + (lane & 7) + ((lane >> 4) << 3));
            const uint32_t bcol = (uint32_t)(kb + ((lane >> 3) & 1) * 8);
            #pragma unroll
            for (int p = 0; p < 2; p++) {
                uint32_t off = ((brow + p * 16) * 40u + bcol) * 2u;
                ldmx4(bh4[p], sB  + off);
                ldmx4(bl4[p], sBl + off);
            }
            #pragma unroll
            for (int m = 0; m < 4; m++) {
                #pragma unroll
                for (int n = 0; n < 4; n++) {
                    uint32_t b0 = bh4[n >> 1][(n & 1) * 2];
                    uint32_t b1 = bh4[n >> 1][(n & 1) * 2 + 1];
                    uint32_t c0 = bl4[n >> 1][(n & 1) * 2];
                    uint32_t c1 = bl4[n >> 1][(n & 1) * 2 + 1];
                    mma16816(acc[m][n], ah4[m], b0, b1);
                    mma16816(acc[m][n], ah4[m], c0, c1);
                    mma16816(acc[m][n], al4[m], b0, b1);
                }
            }
        }
        __syncthreads();
    }

    const int r0 = m0 + wr * 64 + (lane >> 2);
    const int cc = n0 + wc * 32 + (lane & 3) * 2;
    #pragma unroll
    for (int m = 0; m < 4; m++) {
        #pragma unroll
        for (int n = 0; n < 4; n++) {
            float* p0 = C + (size_t)(r0 + m * 16) * N + cc + n * 8;
            float* p1 = C + (size_t)(r0 + m * 16 + 8) * N + cc + n * 8;
            *(float2*)p0 = make_float2(acc[m][n][0], acc[m][n][1]);
            *(float2*)p1 = make_float2(acc[m][n][2], acc[m][n][3]);
        }
    }
}

// ============================================================
// chunk_state split-K: grid (NC, BH, 2); each block does 64 j-rows
// ============================================================
__global__ __launch_bounds__(256)
void chunk_state(const float* __restrict__ kmat, const float* __restrict__ vmat,
                 float* __restrict__ P2)
{
    __shared__ float Ks[64][68];
    __shared__ float Vs[64][68];
    const int ch = blockIdx.x;
    const int bh = blockIdx.y;
    const int z  = blockIdx.z;
    const int b = bh >> 4, h = bh & 15;
    const float lg = log2f(1.f - exp2f(-5.f - (float)h));
    const int tid = threadIdx.x;
    const int j0 = ch * CH + z * 64;

    const float* kbase = kmat + ((size_t)(b*TT + j0))*DM + h*DH;
    const float* vbase = vmat + ((size_t)(b*TT + j0))*DM + h*DH;
    for (int s = tid; s < 64*16; s += 256) {
        int row = s >> 4, c4 = (s & 15) << 2;
        float sc = exp2f(lg * (float)(CH - z*64 - row));
        float4 kk = *(const float4*)(kbase + (size_t)row*DM + c4);
        Ks[row][c4+0] = kk.x*sc; Ks[row][c4+1] = kk.y*sc;
        Ks[row][c4+2] = kk.z*sc; Ks[row][c4+3] = kk.w*sc;
        float4 vv = *(const float4*)(vbase + (size_t)row*DM + c4);
        *(float4*)&Vs[row][c4] = vv;
    }
    __syncthreads();

    const int tr = tid >> 4, tc = tid & 15;
    float acc[4][4];
    #pragma unroll
    for (int i = 0; i < 4; i++)
        #pragma unroll
        for (int j = 0; j < 4; j++) acc[i][j] = 0.f;

    #pragma unroll 4
    for (int j = 0; j < 64; j++) {
        float ar[4], br[4];
        *(float4*)&ar[0] = *(const float4*)&Ks[j][tr*4];
        *(float4*)&br[0] = *(const float4*)&Vs[j][tc*4];
        #pragma unroll
        for (int i = 0; i < 4; i++)
            #pragma unroll
            for (int jj = 0; jj < 4; jj++)
                acc[i][jj] += ar[i] * br[jj];
    }

    float* pbase = P2 + ((size_t)((bh*NC + ch)*2 + z))*DH*DH;
    #pragma unroll
    for (int i = 0; i < 4; i++)
        *(float4*)(pbase + (tr*4 + i)*DH + tc*4) =
            make_float4(acc[i][0], acc[i][1], acc[i][2], acc[i][3]);
}

// ============================================================
// state_scan: parallel over elements. grid (16, 32) x 256 threads.
// each thread owns one state element; full unroll -> loads hoisted.
// ============================================================
__global__ __launch_bounds__(256)
void state_scan(const float* __restrict__ P2, float* __restrict__ S)
{
    const int bh = blockIdx.y;
    const int e = blockIdx.x * 256 + threadIdx.x;   // 0..4095
    const int h = bh & 15;
    const float lg = log2f(1.f - exp2f(-5.f - (float)h));
    const float gC = exp2f(lg * (float)CH);

    float s = 0.f;
    #pragma unroll
    for (int n = 0; n < NC; n++) {
        const size_t sb = ((size_t)(bh*NC + n))*DH*DH;
        const size_t pb = ((size_t)(bh*NC + n))*2*DH*DH;
        S[sb + e] = s * 0.125f;
        float p0 = P2[pb + e];
        float p1 = P2[pb + DH*DH + e];
        s = gC * s + p0 + p1;
    }
}

// ============================================================
// retention_chunk
// ============================================================
#define RET_SMEM_FLOATS (64*132 + 64*68 + 64*68 + 128*68)

__global__ __launch_bounds__(256)
void retention_chunk(const float* __restrict__ q, const float* __restrict__ kmat,
                     const float* __restrict__ vmat, const float* __restrict__ Sg,
                     float* __restrict__ y)
{
    extern __shared__ float smf[];
    float (*QT)[132] = (float (*)[132])smf;
    float (*KT)[68]  = (float (*)[68])(smf + 64*132);
    float (*Vs)[68]  = (float (*)[68])(smf + 64*132 + 64*68);
    float (*Ss)[68]  = (float (*)[68])(smf + 64*132 + 2*64*68);

    const int it = blockIdx.x;
    const int bh = blockIdx.y;
    const int b = bh >> 4, h = bh & 15;
    const int i0 = it * CH;
    const float lg = log2f(1.f - exp2f(-5.f - (float)h));
    const int tid = threadIdx.x;
    const int tr = tid >> 4;
    const int tc = tid & 15;

    const float* qbase = q + ((size_t)(b*TT + i0))*DM + h*DH;
    for (int s = tid; s < CH*16; s += 256) {
        int row = s >> 4, c4 = (s & 15) << 2;
        float4 a = *(const float4*)(qbase + (size_t)row*DM + c4);
        float sc = exp2f(lg * (float)row);
        QT[c4+0][row] = a.x*sc; QT[c4+1][row] = a.y*sc;
        QT[c4+2][row] = a.z*sc; QT[c4+3][row] = a.w*sc;
    }
    const float* sbase = Sg + ((size_t)(bh*NC + it))*DH*DH;
    for (int s = tid; s < 64*16; s += 256) {
        int row = s >> 4, c4 = (s & 15) << 2;
        *(float4*)&KT[row][c4] = *(const float4*)(sbase + row*DH + c4);
    }
    __syncthreads();

    float accy[8][4];
    #pragma unroll
    for (int i = 0; i < 8; i++)
        #pragma unroll
        for (int j = 0; j < 4; j++) accy[i][j] = 0.f;

    #pragma unroll 8
    for (int a = 0; a < DH; a++) {
        float ar[8], br[4];
        *(float4*)&ar[0] = *(const float4*)&QT[a][tr*8];
        *(float4*)&ar[4] = *(const float4*)&QT[a][tr*8+4];
        *(float4*)&br[0] = *(const float4*)&KT[a][tc*4];
        #pragma unroll
        for (int i = 0; i < 8; i++)
            #pragma unroll
            for (int j = 0; j < 4; j++)
                accy[i][j] += ar[i] * br[j];
    }

    #pragma unroll
    for (int jt = 0; jt < 2; jt++) {
        const int j0 = i0 + (jt << 6);
        const int diffbase = -(jt << 6);
        const float* kbase = kmat + ((size_t)(b*TT + j0))*DM + h*DH;
        const float* vbase = vmat + ((size_t)(b*TT + j0))*DM + h*DH;
        __syncthreads();
        for (int s = tid; s < 64*16; s += 256) {
            int row = s >> 4, c4 = (s & 15) << 2;
            float sc = exp2f(-lg * (float)row);
            float4 kk = *(const float4*)(kbase + (size_t)row*DM + c4);
            KT[c4+0][row] = kk.x*sc; KT[c4+1][row] = kk.y*sc;
            KT[c4+2][row] = kk.z*sc; KT[c4+3][row] = kk.w*sc;
            float4 vv = *(const float4*)(vbase + (size_t)row*DM + c4);
            *(float4*)&Vs[row][c4] = vv;
        }
        __syncthreads();

        float acc1[8][4];
        #pragma unroll
        for (int i = 0; i < 8; i++)
            #pragma unroll
            for (int j = 0; j < 4; j++) acc1[i][j] = 0.f;
        #pragma unroll 8
        for (int c = 0; c < DH; c++) {
            float ar[8], br[4];
            *(float4*)&ar[0] = *(const float4*)&QT[c][tr*8];
            *(float4*)&ar[4] = *(const float4*)&QT[c][tr*8+4];
            *(float4*)&br[0] = *(const float4*)&KT[c][tc*4];
            #pragma unroll
            for (int i = 0; i < 8; i++)
                #pragma unroll
                for (int j = 0; j < 4; j++)
                    acc1[i][j] += ar[i] * br[j];
        }

        const float base = exp2f(lg * (float)diffbase) * 0.125f;
        #pragma unroll
        for (int i = 0; i < 8; i++) {
            const int ir = tr*8 + i;
            float o0 = acc1[i][0]*base, o1 = acc1[i][1]*base;
            float o2 = acc1[i][2]*base, o3 = acc1[i][3]*base;
            int d0 = diffbase + ir - (tc*4);
            if (d0     < 0) o0 = 0.f;
            if (d0 - 1 < 0) o1 = 0.f;
            if (d0 - 2 < 0) o2 = 0.f;
            if (d0 - 3 < 0) o3 = 0.f;
            *(float4*)&Ss[ir][tc*4] = make_float4(o0, o1, o2, o3);
        }
        __syncthreads();

        #pragma unroll 8
        for (int jr = 0; jr < 64; jr++) {
            float br[4];
            *(float4*)&br[0] = *(const float4*)&Vs[jr][tc*4];
            #pragma unroll
            for (int i = 0; i < 8; i++) {
                float sv = Ss[tr*8+i][jr];
                accy[i][0] += sv * br[0];
                accy[i][1] += sv * br[1];
                accy[i][2] += sv * br[2];
                accy[i][3] += sv * br[3];
            }
        }
    }

    float* ybase = y + ((size_t)(b*TT + i0))*DM + h*DH;
    #pragma unroll
    for (int i = 0; i < 8; i++) {
        *(float4*)(ybase + (size_t)(tr*8 + i)*DM + tc*4) =
            make_float4(accy[i][0], accy[i][1], accy[i][2], accy[i][3]);
    }
}

// ============================================================
// GroupNorm: phase-1 partial reduce + fused (stats + apply + split)
// ============================================================
__global__ void gn_reduce1(const float* __restrict__ y, float* __restrict__ part)
{
    const int bh = blockIdx.x;
    const int slab = blockIdx.y;
    const int b = bh >> 4, h = bh & 15;
    const float* base = y + (size_t)b*TT*DM + (size_t)slab*(TT/8)*DM + h*DH;
    float s = 0.f, s2 = 0.f;
    for (int sl = threadIdx.x; sl < (TT/8)*16; sl += blockDim.x) {
        int t = sl >> 4, c4 = (sl & 15) << 2;
        float4 vv = *(const float4*)(base + (size_t)t*DM + c4);
        s  += vv.x + vv.y + vv.z + vv.w;
        s2 += vv.x*vv.x + vv.y*vv.y + vv.z*vv.z + vv.w*vv.w;
    }
    #pragma unroll
    for (int o = 16; o > 0; o >>= 1) {
        s  += __shfl_down_sync(0xffffffffu, s,  o);
        s2 += __shfl_down_sync(0xffffffffu, s2, o);
    }
    __shared__ float rs[32], rs2[32];
    const int wid = threadIdx.x >> 5, lid = threadIdx.x & 31;
    if (lid == 0) { rs[wid] = s; rs2[wid] = s2; }
    __syncthreads();
    if (wid == 0) {
        const int nw = blockDim.x >> 5;
        s  = (lid < nw) ? rs[lid]  : 0.f;
        s2 = (lid < nw) ? rs2[lid] : 0.f;
        #pragma unroll
        for (int o = 16; o > 0; o >>= 1) {
            s  += __shfl_down_sync(0xffffffffu, s,  o);
            s2 += __shfl_down_sync(0xffffffffu, s2, o);
        }
        if (lid == 0) {
            part[(bh*8 + slab)*2]   = s;
            part[(bh*8 + slab)*2+1] = s2;
        }
    }
}

// fused: stats from partials + normalize + bf16 split
__global__ void gn_apply_split(const float* __restrict__ y, const float* __restrict__ part,
                               const float* __restrict__ gw, const float* __restrict__ gb,
                               __nv_bfloat16* __restrict__ hi, __nv_bfloat16* __restrict__ lo)
{
    size_t e = ((size_t)blockIdx.x * blockDim.x + threadIdx.x) * 4;
    int col = (int)(e % DM);
    size_t row = e / DM;
    int b = (int)(row / TT);
    int g = b * 16 + (col >> 6);
    float s = 0.f, s2 = 0.f;
    #pragma unroll
    for (int i = 0; i < 8; i++) {
        s  += part[(g*8 + i)*2];
        s2 += part[(g*8 + i)*2+1];
    }
    const float invN = 1.f / (float)(TT * DH);
    float mean = s * invN;
    float rstd = rsqrtf(s2 * invN - mean * mean + 1e-5f);
    float4 vv = *(const float4*)(y + e);
    float4 w4 = *(const float4*)(gw + col);
    float4 b4 = *(const float4*)(gb + col);
    float o0 = (vv.x - mean) * rstd * w4.x + b4.x;
    float o1 = (vv.y - mean) * rstd * w4.y + b4.y;
    float o2 = (vv.z - mean) * rstd * w4.z + b4.z;
    float o3 = (vv.w - mean) * rstd * w4.w + b4.w;
    __nv_bfloat16 h0, h1, h2, h3, l0, l1, l2, l3;
    split1(o0, h0, l0); split1(o1, h1, l1);
    split1(o2, h2, l2); split1(o3, h3, l3);
    __nv_bfloat162* hp = (__nv_bfloat162*)(hi + e);
    __nv_bfloat162* lp = (__nv_bfloat162*)(lo + e);
    hp[0] = __nv_bfloat162(h0, h1); hp[1] = __nv_bfloat162(h2, h3);
    lp[0] = __nv_bfloat162(l0, l1); lp[1] = __nv_bfloat162(l2, l3);
}

// ============================================================
extern "C" void kernel_launch(void* const* d_in, const int* in_sizes, int n_in,
                              void* d_out, int out_size)
{
    const float* x  = (const float*)d_in[0];
    const float* Wq = (const float*)d_in[1];
    const float* Wk = (const float*)d_in[2];
    const float* Wv = (const float*)d_in[3];
    const float* Wo = (const float*)d_in[4];
    const float* gw = (const float*)d_in[5];
    const float* gb = (const float*)d_in[6];
    float* out = (float*)d_out;

    float *q, *k, *v, *y, *pt, *P2, *S;
    __nv_bfloat16 *ah, *al, *wh, *wl;
    cudaGetSymbolAddress((void**)&q,  g_q);
    cudaGetSymbolAddress((void**)&k,  g_k);
    cudaGetSymbolAddress((void**)&v,  g_v);
    cudaGetSymbolAddress((void**)&y,  g_y);
    cudaGetSymbolAddress((void**)&pt, g_part);
    cudaGetSymbolAddress((void**)&P2, g_P2);
    cudaGetSymbolAddress((void**)&S,  g_S);
    cudaGetSymbolAddress((void**)&ah, g_ah);
    cudaGetSymbolAddress((void**)&al, g_al);
    cudaGetSymbolAddress((void**)&wh, g_wh);
    cudaGetSymbolAddress((void**)&wl, g_wl);

    const int ret_smem = RET_SMEM_FLOATS * (int)sizeof(float);
    cudaFuncSetAttribute(retention_chunk, cudaFuncAttributeMaxDynamicSharedMemorySize, ret_smem);
    cudaFuncSetAttribute(gemm_mma, cudaFuncAttributeMaxDynamicSharedMemorySize, GSM_BYTES);

    // one merged split launch (x + 4 weights)
    split_all<<<dim3(1024, 8), 256>>>(x, Wq, Wk, Wv, Wo, ah, al, wh, wl);

    // batched QKV GEMM
    dim3 gq(DM/128, MT/128, 3);
    gemm_mma<<<gq, 256, GSM_BYTES>>>(ah, al, wh, wl, q, k, v, MT, DM, DM, 0);

    chunk_state<<<dim3(NC, BB*NH, 2), 256>>>(k, v, P2);
    state_scan<<<dim3(16, BB*NH), 256>>>(P2, S);
    retention_chunk<<<dim3(NC, BB*NH), 256, ret_smem>>>(q, k, v, S, y);

    gn_reduce1<<<dim3(BB*NH, 8), 512>>>(y, pt);
    gn_apply_split<<<(MT*DM)/(4*256), 256>>>(y, pt, gw, gb, ah, al);

    // output GEMM (weight index 3)
    dim3 go(DM/128, MT/128, 1);
    gemm_mma<<<go, 256, GSM_BYTES>>>(ah, al, wh, wl, out, out, out, MT, DM, DM, 3);
}